// round 6
// baseline (speedup 1.0000x reference)
#include <cuda_runtime.h>
#include <cuda_bf16.h>
#include <cstdint>
#include <math.h>

#define S_LEN   2048
#define B_SZ    2
#define NH      16
#define HD      128
#define M_TOT   (B_SZ * S_LEN)     /* 4096 */
#define HIDDEN  2048
#define LATENT  512

// ---------------- scratch (device globals: no allocation allowed) ----------------
__device__ float g_kv_lat[M_TOT * LATENT];
__device__ float g_q_lat [M_TOT * LATENT];
__device__ float g_k_half[M_TOT * (NH * 64)];
__device__ float g_q_half[M_TOT * (NH * 64)];
__device__ float g_k_rope[M_TOT * (NH * 64)];
__device__ float g_q_rope[M_TOT * (NH * 64)];
__device__ float g_v     [M_TOT * HIDDEN];
__device__ float g_y     [M_TOT * HIDDEN];
__device__ float g_cos   [S_LEN * 32];
__device__ float g_sin   [S_LEN * 32];

// bf16 hi/lo split buffers
__device__ __nv_bfloat16 g_xb_hi[M_TOT * HIDDEN];   // also reused for Y
__device__ __nv_bfloat16 g_xb_lo[M_TOT * HIDDEN];
__device__ __nv_bfloat16 g_kvb_hi[M_TOT * LATENT];
__device__ __nv_bfloat16 g_kvb_lo[M_TOT * LATENT];
__device__ __nv_bfloat16 g_qb_hi[M_TOT * LATENT];
__device__ __nv_bfloat16 g_qb_lo[M_TOT * LATENT];

// attention operands (bf16 hi/lo)
__device__ __nv_bfloat16 g_Qh[M_TOT * HIDDEN];
__device__ __nv_bfloat16 g_Ql[M_TOT * HIDDEN];
__device__ __nv_bfloat16 g_Kh[M_TOT * HIDDEN];
__device__ __nv_bfloat16 g_Kl[M_TOT * HIDDEN];
__device__ __nv_bfloat16 g_Vth[B_SZ * NH * HD * S_LEN];  // [b][h][d][s]
__device__ __nv_bfloat16 g_Vtl[B_SZ * NH * HD * S_LEN];

// transposed weights [N,K] bf16 hi/lo, one pool with offsets
#define OFF_KV_D   0
#define OFF_Q_D    1048576
#define OFF_ROPE_K 2097152
#define OFF_K_U    4194304
#define OFF_Q_U    4718592
#define OFF_ROPE_Q 5242880
#define OFF_V_U    5767168
#define OFF_O      6815744
#define W_POOL     11010048
__device__ __nv_bfloat16 g_wb_hi[W_POOL];
__device__ __nv_bfloat16 g_wb_lo[W_POOL];

// ================= helpers =================
__device__ __forceinline__ uint32_t smem_u32(const void* p) {
    uint32_t a;
    asm("{ .reg .u64 t; cvta.to.shared.u64 t, %1; cvt.u32.u64 %0, t; }" : "=r"(a) : "l"(p));
    return a;
}

__device__ __forceinline__ void ldmx4(uint32_t* r, uint32_t addr) {
    asm volatile("ldmatrix.sync.aligned.m8n8.x4.shared.b16 {%0,%1,%2,%3}, [%4];"
        : "=r"(r[0]), "=r"(r[1]), "=r"(r[2]), "=r"(r[3]) : "r"(addr));
}

__device__ __forceinline__ void mma16816(float* c, const uint32_t* a, uint32_t b0, uint32_t b1) {
    asm volatile(
        "mma.sync.aligned.m16n8k16.row.col.f32.bf16.bf16.f32 "
        "{%0,%1,%2,%3}, {%4,%5,%6,%7}, {%8,%9}, {%0,%1,%2,%3};"
        : "+f"(c[0]), "+f"(c[1]), "+f"(c[2]), "+f"(c[3])
        : "r"(a[0]), "r"(a[1]), "r"(a[2]), "r"(a[3]), "r"(b0), "r"(b1));
}

__device__ __forceinline__ void cp16(uint32_t dst, const void* src) {
    unsigned long long g = (unsigned long long)__cvta_generic_to_global(src);
    asm volatile("cp.async.cg.shared.global [%0], [%1], 16;" :: "r"(dst), "l"(g) : "memory");
}

__device__ __forceinline__ void bsplit2(float a, float b, uint32_t& hi, uint32_t& lo) {
    __nv_bfloat162 h, l;
    h.x = __float2bfloat16(a); l.x = __float2bfloat16(a - __bfloat162float(h.x));
    h.y = __float2bfloat16(b); l.y = __float2bfloat16(b - __bfloat162float(h.y));
    hi = *(uint32_t*)&h; lo = *(uint32_t*)&l;
}

// ================= conversion kernels =================
__global__ __launch_bounds__(256) void aconv_kernel(
    const float* __restrict__ A, __nv_bfloat16* __restrict__ hi,
    __nv_bfloat16* __restrict__ lo, int n4)
{
    int i = blockIdx.x * 256 + threadIdx.x;
    if (i >= n4) return;
    float4 v = ((const float4*)A)[i];
    __nv_bfloat162 h01, h23, l01, l23;
    h01.x = __float2bfloat16(v.x); l01.x = __float2bfloat16(v.x - __bfloat162float(h01.x));
    h01.y = __float2bfloat16(v.y); l01.y = __float2bfloat16(v.y - __bfloat162float(h01.y));
    h23.x = __float2bfloat16(v.z); l23.x = __float2bfloat16(v.z - __bfloat162float(h23.x));
    h23.y = __float2bfloat16(v.w); l23.y = __float2bfloat16(v.w - __bfloat162float(h23.y));
    uint2 hv, lv;
    hv.x = *(uint32_t*)&h01; hv.y = *(uint32_t*)&h23;
    lv.x = *(uint32_t*)&l01; lv.y = *(uint32_t*)&l23;
    ((uint2*)hi)[i] = hv;
    ((uint2*)lo)[i] = lv;
}

// W[K][N] fp32 -> Wt[N][K] bf16 hi/lo (transpose via smem tile)
__global__ void wconv_kernel(const float* __restrict__ W, __nv_bfloat16* __restrict__ hi,
                             __nv_bfloat16* __restrict__ lo, int K, int N)
{
    __shared__ float t[32][33];
    int n0 = blockIdx.x * 32, k0 = blockIdx.y * 32;
    int tx = threadIdx.x, ty = threadIdx.y;
    for (int j = ty; j < 32; j += 8)
        t[j][tx] = W[(size_t)(k0 + j) * N + n0 + tx];
    __syncthreads();
    for (int j = ty; j < 32; j += 8) {
        float v = t[tx][j];
        __nv_bfloat16 h = __float2bfloat16(v);
        size_t o = (size_t)(n0 + j) * K + k0 + tx;
        hi[o] = h;
        lo[o] = __float2bfloat16(v - __bfloat162float(h));
    }
}

// V fp32 [b*S+s][h*128+d] -> Vt bf16 hi/lo [(b*16+h)*128+d][s]
__global__ void vtconv_kernel(const float* __restrict__ V,
                              __nv_bfloat16* __restrict__ Vh, __nv_bfloat16* __restrict__ Vl)
{
    __shared__ float t[32][33];
    int bh_ = blockIdx.z;
    int b = bh_ >> 4, h = bh_ & 15;
    int s0 = blockIdx.x * 32, d0 = blockIdx.y * 32;
    int tx = threadIdx.x, ty = threadIdx.y;
    for (int j = ty; j < 32; j += 8)
        t[j][tx] = V[(size_t)(b * S_LEN + s0 + j) * HIDDEN + h * HD + d0 + tx];
    __syncthreads();
    for (int j = ty; j < 32; j += 8) {
        float v = t[tx][j];   // V[s0+tx][d0+j]
        __nv_bfloat16 hh = __float2bfloat16(v);
        size_t o = ((size_t)bh_ * HD + d0 + j) * S_LEN + s0 + tx;
        Vh[o] = hh;
        Vl[o] = __float2bfloat16(v - __bfloat162float(hh));
    }
}

// ================= HMMA split-bf16 GEMM (proven in R4) =================
#define G_STAGE 32768
#define G_SMEM  (3 * G_STAGE)

__device__ __forceinline__ void gemm_load_chunk(
    uint32_t stage, int tid,
    const __nv_bfloat16* Ahi, const __nv_bfloat16* Alo,
    const __nv_bfloat16* Bhi, const __nv_bfloat16* Blo,
    int m0, int n0, int kc, int K)
{
#pragma unroll
    for (int i = 0; i < 8; i++) {
        int f = i * 256 + tid;
        int t = f >> 9;
        int r = (f >> 2) & 127;
        int u = f & 3;
        const __nv_bfloat16* bp = (t == 0) ? Ahi : (t == 1) ? Alo : (t == 2) ? Bhi : Blo;
        int row = ((t < 2) ? m0 : n0) + r;
        const __nv_bfloat16* src = bp + (size_t)row * K + kc + u * 8;
        uint32_t dst = stage + t * 8192 + r * 64 + ((u ^ ((r >> 1) & 3)) * 16);
        cp16(dst, src);
    }
    asm volatile("cp.async.commit_group;" ::: "memory");
}

__global__ __launch_bounds__(256) void hmma_gemm_kernel(
    const __nv_bfloat16* __restrict__ Ahi, const __nv_bfloat16* __restrict__ Alo,
    const __nv_bfloat16* __restrict__ Bhi, const __nv_bfloat16* __restrict__ Blo,
    float* __restrict__ C, int M, int N, int K)
{
    extern __shared__ __align__(128) char smem[];
    uint32_t sb = smem_u32(smem);
    const int tid = threadIdx.x, lane = tid & 31, wid = tid >> 5;
    const int wm = wid >> 2, wn = wid & 3;
    const int m0 = blockIdx.y << 7, n0 = blockIdx.x << 7;
    const int q = lane >> 3, rr = lane & 7;

    uint32_t offA[4][2], offB[2][2];
#pragma unroll
    for (int mi = 0; mi < 4; mi++)
#pragma unroll
        for (int ks = 0; ks < 2; ks++) {
            int row = wm * 64 + mi * 16 + (q & 1) * 8 + rr;
            int u = ks * 2 + (q >> 1);
            offA[mi][ks] = row * 64 + ((u ^ ((row >> 1) & 3)) * 16);
        }
#pragma unroll
    for (int n2 = 0; n2 < 2; n2++)
#pragma unroll
        for (int ks = 0; ks < 2; ks++) {
            int row = wn * 32 + n2 * 16 + (q >> 1) * 8 + rr;
            int u = ks * 2 + (q & 1);
            offB[n2][ks] = row * 64 + ((u ^ ((row >> 1) & 3)) * 16);
        }

    float acc[4][4][4];
#pragma unroll
    for (int a = 0; a < 4; a++)
#pragma unroll
        for (int b = 0; b < 4; b++)
#pragma unroll
            for (int cc = 0; cc < 4; cc++) acc[a][b][cc] = 0.0f;

    const int NC = K >> 5;

    gemm_load_chunk(sb,           tid, Ahi, Alo, Bhi, Blo, m0, n0, 0,  K);
    gemm_load_chunk(sb + G_STAGE, tid, Ahi, Alo, Bhi, Blo, m0, n0, 32, K);

    int sidx = 0;
    for (int c = 0; c < NC; c++) {
        if (c + 1 < NC) asm volatile("cp.async.wait_group 1;" ::: "memory");
        else            asm volatile("cp.async.wait_group 0;" ::: "memory");
        __syncthreads();

        if (c + 2 < NC) {
            int s2 = sidx + 2; if (s2 >= 3) s2 -= 3;
            gemm_load_chunk(sb + s2 * G_STAGE, tid, Ahi, Alo, Bhi, Blo,
                            m0, n0, (c + 2) << 5, K);
        }

        const uint32_t stage = sb + sidx * G_STAGE;
#pragma unroll
        for (int ks = 0; ks < 2; ks++) {
            uint32_t ah[4][4], al[4][4], bh[2][4], bl[2][4];
#pragma unroll
            for (int mi = 0; mi < 4; mi++) ldmx4(ah[mi], stage + offA[mi][ks]);
#pragma unroll
            for (int mi = 0; mi < 4; mi++) ldmx4(al[mi], stage + 8192 + offA[mi][ks]);
#pragma unroll
            for (int n2 = 0; n2 < 2; n2++) ldmx4(bh[n2], stage + 16384 + offB[n2][ks]);
#pragma unroll
            for (int n2 = 0; n2 < 2; n2++) ldmx4(bl[n2], stage + 24576 + offB[n2][ks]);
#pragma unroll
            for (int mi = 0; mi < 4; mi++) {
#pragma unroll
                for (int ni = 0; ni < 4; ni++) {
                    const int n2 = ni >> 1, hf = ni & 1;
                    mma16816(acc[mi][ni], ah[mi], bh[n2][hf * 2], bh[n2][hf * 2 + 1]);
                    mma16816(acc[mi][ni], ah[mi], bl[n2][hf * 2], bl[n2][hf * 2 + 1]);
                    mma16816(acc[mi][ni], al[mi], bh[n2][hf * 2], bh[n2][hf * 2 + 1]);
                }
            }
        }
        __syncthreads();
        sidx++; if (sidx == 3) sidx = 0;
    }

    const int cm = m0 + wm * 64 + (lane >> 2);
    const int cn = n0 + wn * 32 + (lane & 3) * 2;
#pragma unroll
    for (int mi = 0; mi < 4; mi++) {
#pragma unroll
        for (int ni = 0; ni < 4; ni++) {
            float* p0 = C + (size_t)(cm + mi * 16)     * N + cn + ni * 8;
            float* p1 = C + (size_t)(cm + mi * 16 + 8) * N + cn + ni * 8;
            *(float2*)p0 = make_float2(acc[mi][ni][0], acc[mi][ni][1]);
            *(float2*)p1 = make_float2(acc[mi][ni][2], acc[mi][ni][3]);
        }
    }
}

// ---------------- RoPE cos/sin table ----------------
__global__ void rope_table_kernel(float* __restrict__ cosT, float* __restrict__ sinT) {
    int idx = blockIdx.x * blockDim.x + threadIdx.x;
    if (idx >= S_LEN * 32) return;
    int s = idx >> 5;
    int i = idx & 31;
    double inv = exp(-((double)i / 32.0) * log(10000.0));
    double a   = (double)s * inv;
    cosT[idx] = (float)cos(a);
    sinT[idx] = (float)sin(a);
}

// ---------------- assemble q/k (RoPE) -> bf16 hi/lo, Q prescaled ----------------
__global__ __launch_bounds__(256) void assemble_qk_kernel(
    const float* __restrict__ qh, const float* __restrict__ qr,
    const float* __restrict__ kh, const float* __restrict__ kr,
    const float* __restrict__ cosT, const float* __restrict__ sinT,
    __nv_bfloat16* __restrict__ Qh, __nv_bfloat16* __restrict__ Ql,
    __nv_bfloat16* __restrict__ Kh, __nv_bfloat16* __restrict__ Kl)
{
    const float scale = 0.08838834764831845f;   // 1/sqrt(128)
    int idx = blockIdx.x * blockDim.x + threadIdx.x;
    if (idx >= M_TOT * 1024) return;
    int row = idx >> 10;
    int hj  = idx & 1023;
    int h = hj >> 6;
    int j = hj & 63;
    int s = row & (S_LEN - 1);

    size_t o0 = (size_t)row * HIDDEN + h * HD + j;
    size_t o1 = o0 + 64;

    float qn = qh[idx] * scale;
    float kn = kh[idx];
    __nv_bfloat16 t;
    t = __float2bfloat16(qn); Qh[o0] = t; Ql[o0] = __float2bfloat16(qn - __bfloat162float(t));
    t = __float2bfloat16(kn); Kh[o0] = t; Kl[o0] = __float2bfloat16(kn - __bfloat162float(t));

    int fi = j & 31;
    float c  = cosT[s * 32 + fi];
    float sn = sinT[s * 32 + fi];
    int pair = (j < 32) ? idx + 32 : idx - 32;
    float sgn = (j < 32) ? -1.0f : 1.0f;
    float qv = (qr[idx] * c + sgn * qr[pair] * sn) * scale;
    float kv =  kr[idx] * c + sgn * kr[pair] * sn;
    t = __float2bfloat16(qv); Qh[o1] = t; Ql[o1] = __float2bfloat16(qv - __bfloat162float(t));
    t = __float2bfloat16(kv); Kh[o1] = t; Kl[o1] = __float2bfloat16(kv - __bfloat162float(t));
}

// ================= HMMA flash attention =================
// CTA: 64 q-rows x one (b,h); 4 warps, each 16 q-rows. K-tile = 64 keys.
// Smem: Qhi|Qlo (16KB each) + 2 stages x (Khi|Klo|Vthi|Vtlo) (16KB each) = 160KB.
#define A_SMEM (32768 + 2 * 65536)

__device__ __forceinline__ void attn_load_tile(
    uint32_t stg, int tid, int b, int h, int k0,
    const __nv_bfloat16* Kh, const __nv_bfloat16* Kl,
    const __nv_bfloat16* Vh, const __nv_bfloat16* Vl)
{
#pragma unroll
    for (int i = 0; i < 32; i++) {
        int f = i * 128 + tid;
        int t = f >> 10;       // 0:Kh 1:Kl 2:Vh 3:Vl
        int g = f & 1023;
        if (t < 2) {
            int r = g >> 4, u = g & 15;
            const __nv_bfloat16* src = ((t == 0) ? Kh : Kl)
                + (size_t)(b * S_LEN + k0 + r) * HIDDEN + h * HD + u * 8;
            cp16(stg + t * 16384 + r * 256 + ((u ^ (r & 7)) << 4), src);
        } else {
            int d = g >> 3, u = g & 7;
            const __nv_bfloat16* src = ((t == 2) ? Vh : Vl)
                + ((size_t)(b * NH + h) * HD + d) * S_LEN + k0 + u * 8;
            cp16(stg + t * 16384 + d * 128 + ((u ^ (d & 7)) << 4), src);
        }
    }
    asm volatile("cp.async.commit_group;" ::: "memory");
}

__global__ __launch_bounds__(128) void fattn_kernel(
    const __nv_bfloat16* __restrict__ Qh, const __nv_bfloat16* __restrict__ Ql,
    const __nv_bfloat16* __restrict__ Kh, const __nv_bfloat16* __restrict__ Kl,
    const __nv_bfloat16* __restrict__ Vth, const __nv_bfloat16* __restrict__ Vtl,
    float* __restrict__ Y)
{
    extern __shared__ __align__(128) char smem[];
    uint32_t sb = smem_u32(smem);
    const int qt = (S_LEN / 64 - 1) - blockIdx.x;   // long rows first
    const int h = blockIdx.y, b = blockIdx.z;
    const int tid = threadIdx.x, lane = tid & 31, wm = tid >> 5;
    const int q0 = qt * 64;
    const int rr = lane & 7, qq = lane >> 3;
    const int qb0 = qq >> 1, qb1 = qq & 1;

    // load Q tiles (hi+lo)
#pragma unroll
    for (int i = 0; i < 16; i++) {
        int f = i * 128 + tid;
        int t = f >> 10;
        int g = f & 1023;
        int r = g >> 4, u = g & 15;
        const __nv_bfloat16* src = ((t == 0) ? Qh : Ql)
            + (size_t)(b * S_LEN + q0 + r) * HIDDEN + h * HD + u * 8;
        cp16(sb + t * 16384 + r * 256 + ((u ^ (r & 7)) << 4), src);
    }
    asm volatile("cp.async.commit_group;" ::: "memory");

    attn_load_tile(sb + 32768,         tid, b, h, 0,  Kh, Kl, Vth, Vtl);
    if (qt >= 1) attn_load_tile(sb + 32768 + 65536, tid, b, h, 64, Kh, Kl, Vth, Vtl);

    float o[16][4];
#pragma unroll
    for (int j = 0; j < 16; j++)
#pragma unroll
        for (int e = 0; e < 4; e++) o[j][e] = 0.0f;
    float m0 = -1e30f, m1 = -1e30f, l0 = 0.0f, l1 = 0.0f;

    // precomputable pieces
    const int rA = wm * 16 + qb1 * 8 + rr;              // q-row within tile (A frag)
    const uint32_t offQbase = rA * 256;
    const int swA = rA & 7;

    for (int kt = 0; kt <= qt; kt++) {
        if (kt < qt) asm volatile("cp.async.wait_group 1;" ::: "memory");
        else         asm volatile("cp.async.wait_group 0;" ::: "memory");
        __syncthreads();

        const uint32_t stg = sb + 32768 + (kt & 1) * 65536;
        const int k0 = kt * 64;

        // ---- S = Q K^T (3-term split) ----
        float s[8][4];
#pragma unroll
        for (int j = 0; j < 8; j++)
#pragma unroll
            for (int e = 0; e < 4; e++) s[j][e] = 0.0f;

#pragma unroll
        for (int ks = 0; ks < 8; ks++) {
            uint32_t ah[4], al[4];
            uint32_t ua = 2 * ks + qb0;
            uint32_t qoff = offQbase + ((ua ^ swA) << 4);
            ldmx4(ah, sb + qoff);
            ldmx4(al, sb + 16384 + qoff);
#pragma unroll
            for (int n2 = 0; n2 < 4; n2++) {
                int rB = n2 * 16 + qb0 * 8 + rr;
                uint32_t ub = 2 * ks + qb1;
                uint32_t koff = rB * 256 + (((ub ^ (rB & 7))) << 4);
                uint32_t bh[4], bl[4];
                ldmx4(bh, stg + koff);
                ldmx4(bl, stg + 16384 + koff);
                mma16816(s[2 * n2],     ah, bh[0], bh[1]);
                mma16816(s[2 * n2],     ah, bl[0], bl[1]);
                mma16816(s[2 * n2],     al, bh[0], bh[1]);
                mma16816(s[2 * n2 + 1], ah, bh[2], bh[3]);
                mma16816(s[2 * n2 + 1], ah, bl[2], bl[3]);
                mma16816(s[2 * n2 + 1], al, bh[2], bh[3]);
            }
        }

        // ---- causal mask (diagonal tile only) ----
        if (kt == qt) {
            int rbase = q0 + wm * 16 + (lane >> 2);
            int cbase = k0 + (lane & 3) * 2;
#pragma unroll
            for (int j = 0; j < 8; j++) {
                int c0 = cbase + j * 8, c1 = c0 + 1;
                if (c0 > rbase)     s[j][0] = -1e30f;
                if (c1 > rbase)     s[j][1] = -1e30f;
                if (c0 > rbase + 8) s[j][2] = -1e30f;
                if (c1 > rbase + 8) s[j][3] = -1e30f;
            }
        }

        // ---- online softmax ----
        float mt0 = -1e30f, mt1 = -1e30f;
#pragma unroll
        for (int j = 0; j < 8; j++) {
            mt0 = fmaxf(mt0, fmaxf(s[j][0], s[j][1]));
            mt1 = fmaxf(mt1, fmaxf(s[j][2], s[j][3]));
        }
        mt0 = fmaxf(mt0, __shfl_xor_sync(0xffffffffu, mt0, 1));
        mt0 = fmaxf(mt0, __shfl_xor_sync(0xffffffffu, mt0, 2));
        mt1 = fmaxf(mt1, __shfl_xor_sync(0xffffffffu, mt1, 1));
        mt1 = fmaxf(mt1, __shfl_xor_sync(0xffffffffu, mt1, 2));
        float mn0 = fmaxf(m0, mt0), mn1 = fmaxf(m1, mt1);
        float cr0 = __expf(m0 - mn0), cr1 = __expf(m1 - mn1);
        m0 = mn0; m1 = mn1;

        float ps0 = 0.0f, ps1 = 0.0f;
#pragma unroll
        for (int j = 0; j < 8; j++) {
            s[j][0] = __expf(s[j][0] - mn0);
            s[j][1] = __expf(s[j][1] - mn0);
            s[j][2] = __expf(s[j][2] - mn1);
            s[j][3] = __expf(s[j][3] - mn1);
            ps0 += s[j][0] + s[j][1];
            ps1 += s[j][2] + s[j][3];
        }
        ps0 += __shfl_xor_sync(0xffffffffu, ps0, 1);
        ps0 += __shfl_xor_sync(0xffffffffu, ps0, 2);
        ps1 += __shfl_xor_sync(0xffffffffu, ps1, 1);
        ps1 += __shfl_xor_sync(0xffffffffu, ps1, 2);
        l0 = l0 * cr0 + ps0;
        l1 = l1 * cr1 + ps1;
#pragma unroll
        for (int j = 0; j < 16; j++) {
            o[j][0] *= cr0; o[j][1] *= cr0;
            o[j][2] *= cr1; o[j][3] *= cr1;
        }

        // ---- P -> bf16 hi/lo A-fragments ----
        uint32_t phi[4][4], plo[4][4];
#pragma unroll
        for (int ks = 0; ks < 4; ks++) {
            bsplit2(s[2 * ks][0],     s[2 * ks][1],     phi[ks][0], plo[ks][0]);
            bsplit2(s[2 * ks][2],     s[2 * ks][3],     phi[ks][1], plo[ks][1]);
            bsplit2(s[2 * ks + 1][0], s[2 * ks + 1][1], phi[ks][2], plo[ks][2]);
            bsplit2(s[2 * ks + 1][2], s[2 * ks + 1][3], phi[ks][3], plo[ks][3]);
        }

        // ---- O += P @ V (3-term split), B = Vt tiles ----
#pragma unroll
        for (int v2 = 0; v2 < 8; v2++) {
            int rv = v2 * 16 + qb0 * 8 + rr;
            uint32_t vbase = stg + 32768 + rv * 128;
            int swv = rv & 7;
#pragma unroll
            for (int ks = 0; ks < 4; ks++) {
                uint32_t u = 2 * ks + qb1;
                uint32_t voff = (u ^ swv) << 4;
                uint32_t bh[4], bl[4];
                ldmx4(bh, vbase + voff);
                ldmx4(bl, vbase + 16384 + voff);
                float* o0 = o[v2 * 2];
                float* o1 = o[v2 * 2 + 1];
                mma16816(o0, phi[ks], bh[0], bh[1]);
                mma16816(o0, phi[ks], bl[0], bl[1]);
                mma16816(o0, plo[ks], bh[0], bh[1]);
                mma16816(o1, phi[ks], bh[2], bh[3]);
                mma16816(o1, phi[ks], bl[2], bl[3]);
                mma16816(o1, plo[ks], bh[2], bh[3]);
            }
        }

        if (kt + 2 <= qt) {
            __syncthreads();
            attn_load_tile(sb + 32768 + (kt & 1) * 65536, tid, b, h, (kt + 2) * 64,
                           Kh, Kl, Vth, Vtl);
        }
    }

    // ---- epilogue ----
    float inv0 = 1.0f / l0, inv1 = 1.0f / l1;
    int row0 = b * S_LEN + q0 + wm * 16 + (lane >> 2);
    int colb = h * HD + (lane & 3) * 2;
#pragma unroll
    for (int j = 0; j < 16; j++) {
        *(float2*)(Y + (size_t)row0 * HIDDEN + colb + j * 8)
            = make_float2(o[j][0] * inv0, o[j][1] * inv0);
        *(float2*)(Y + (size_t)(row0 + 8) * HIDDEN + colb + j * 8)
            = make_float2(o[j][2] * inv1, o[j][3] * inv1);
    }
}

// ---------------- host ----------------
static void launch_mma(const __nv_bfloat16* Ah, const __nv_bfloat16* Al,
                       const __nv_bfloat16* Bh, const __nv_bfloat16* Bl,
                       float* C, int M, int N, int K)
{
    dim3 grid(N / 128, M / 128);
    hmma_gemm_kernel<<<grid, 256, G_SMEM>>>(Ah, Al, Bh, Bl, C, M, N, K);
}

extern "C" void kernel_launch(void* const* d_in, const int* in_sizes, int n_in,
                              void* d_out, int out_size)
{
    const float* x        = (const float*)d_in[0];
    const float* W_kv_d   = (const float*)d_in[1];
    const float* W_q_d    = (const float*)d_in[2];
    const float* W_k_u    = (const float*)d_in[3];
    const float* W_q_u    = (const float*)d_in[4];
    const float* W_v_u    = (const float*)d_in[5];
    const float* W_rope_k = (const float*)d_in[6];
    const float* W_rope_q = (const float*)d_in[7];
    const float* W_o      = (const float*)d_in[8];
    float* out = (float*)d_out;

    float *kv_lat, *q_lat, *k_half, *q_half, *k_rope, *q_rope, *V, *Y, *cosT, *sinT;
    __nv_bfloat16 *xbh, *xbl, *kvbh, *kvbl, *qbh, *qbl, *wbh, *wbl;
    __nv_bfloat16 *Qh, *Ql, *Kh, *Kl, *Vth, *Vtl;
    cudaGetSymbolAddress((void**)&kv_lat, g_kv_lat);
    cudaGetSymbolAddress((void**)&q_lat,  g_q_lat);
    cudaGetSymbolAddress((void**)&k_half, g_k_half);
    cudaGetSymbolAddress((void**)&q_half, g_q_half);
    cudaGetSymbolAddress((void**)&k_rope, g_k_rope);
    cudaGetSymbolAddress((void**)&q_rope, g_q_rope);
    cudaGetSymbolAddress((void**)&V,      g_v);
    cudaGetSymbolAddress((void**)&Y,      g_y);
    cudaGetSymbolAddress((void**)&cosT,   g_cos);
    cudaGetSymbolAddress((void**)&sinT,   g_sin);
    cudaGetSymbolAddress((void**)&xbh,    g_xb_hi);
    cudaGetSymbolAddress((void**)&xbl,    g_xb_lo);
    cudaGetSymbolAddress((void**)&kvbh,   g_kvb_hi);
    cudaGetSymbolAddress((void**)&kvbl,   g_kvb_lo);
    cudaGetSymbolAddress((void**)&qbh,    g_qb_hi);
    cudaGetSymbolAddress((void**)&qbl,    g_qb_lo);
    cudaGetSymbolAddress((void**)&wbh,    g_wb_hi);
    cudaGetSymbolAddress((void**)&wbl,    g_wb_lo);
    cudaGetSymbolAddress((void**)&Qh,     g_Qh);
    cudaGetSymbolAddress((void**)&Ql,     g_Ql);
    cudaGetSymbolAddress((void**)&Kh,     g_Kh);
    cudaGetSymbolAddress((void**)&Kl,     g_Kl);
    cudaGetSymbolAddress((void**)&Vth,    g_Vth);
    cudaGetSymbolAddress((void**)&Vtl,    g_Vtl);

    cudaFuncSetAttribute(hmma_gemm_kernel, cudaFuncAttributeMaxDynamicSharedMemorySize, G_SMEM);
    cudaFuncSetAttribute(fattn_kernel, cudaFuncAttributeMaxDynamicSharedMemorySize, A_SMEM);

    rope_table_kernel<<<(S_LEN * 32 + 255) / 256, 256>>>(cosT, sinT);

    // weight conversions (fp32 [K,N] -> bf16 hi/lo [N,K])
    dim3 wb(32, 8);
    wconv_kernel<<<dim3( 512/32, 2048/32), wb>>>(W_kv_d,   wbh + OFF_KV_D,   wbl + OFF_KV_D,   2048,  512);
    wconv_kernel<<<dim3( 512/32, 2048/32), wb>>>(W_q_d,    wbh + OFF_Q_D,    wbl + OFF_Q_D,    2048,  512);
    wconv_kernel<<<dim3(1024/32, 2048/32), wb>>>(W_rope_k, wbh + OFF_ROPE_K, wbl + OFF_ROPE_K, 2048, 1024);
    wconv_kernel<<<dim3(1024/32,  512/32), wb>>>(W_k_u,    wbh + OFF_K_U,    wbl + OFF_K_U,     512, 1024);
    wconv_kernel<<<dim3(1024/32,  512/32), wb>>>(W_q_u,    wbh + OFF_Q_U,    wbl + OFF_Q_U,     512, 1024);
    wconv_kernel<<<dim3(1024/32,  512/32), wb>>>(W_rope_q, wbh + OFF_ROPE_Q, wbl + OFF_ROPE_Q,  512, 1024);
    wconv_kernel<<<dim3(2048/32,  512/32), wb>>>(W_v_u,    wbh + OFF_V_U,    wbl + OFF_V_U,     512, 2048);
    wconv_kernel<<<dim3(2048/32, 2048/32), wb>>>(W_o,      wbh + OFF_O,      wbl + OFF_O,      2048, 2048);

    // x -> bf16 split
    aconv_kernel<<<(M_TOT * HIDDEN / 4 + 255) / 256, 256>>>(x, xbh, xbl, M_TOT * HIDDEN / 4);

    // level 1 GEMMs (K=2048)
    launch_mma(xbh, xbl, wbh + OFF_KV_D,   wbl + OFF_KV_D,   kv_lat, M_TOT,  512, 2048);
    launch_mma(xbh, xbl, wbh + OFF_Q_D,    wbl + OFF_Q_D,    q_lat,  M_TOT,  512, 2048);
    launch_mma(xbh, xbl, wbh + OFF_ROPE_K, wbl + OFF_ROPE_K, k_rope, M_TOT, 1024, 2048);

    // latents -> bf16 split
    aconv_kernel<<<(M_TOT * LATENT / 4 + 255) / 256, 256>>>(kv_lat, kvbh, kvbl, M_TOT * LATENT / 4);
    aconv_kernel<<<(M_TOT * LATENT / 4 + 255) / 256, 256>>>(q_lat,  qbh,  qbl,  M_TOT * LATENT / 4);

    // level 2 GEMMs (K=512)
    launch_mma(kvbh, kvbl, wbh + OFF_K_U,    wbl + OFF_K_U,    k_half, M_TOT, 1024, 512);
    launch_mma(qbh,  qbl,  wbh + OFF_Q_U,    wbl + OFF_Q_U,    q_half, M_TOT, 1024, 512);
    launch_mma(qbh,  qbl,  wbh + OFF_ROPE_Q, wbl + OFF_ROPE_Q, q_rope, M_TOT, 1024, 512);
    launch_mma(kvbh, kvbl, wbh + OFF_V_U,    wbl + OFF_V_U,    V,      M_TOT, 2048, 512);

    // V -> Vt bf16 hi/lo; q/k assemble -> bf16 hi/lo (Q prescaled)
    vtconv_kernel<<<dim3(S_LEN / 32, HD / 32, B_SZ * NH), wb>>>(V, Vth, Vtl);
    assemble_qk_kernel<<<(M_TOT * 1024 + 255) / 256, 256>>>(
        q_half, q_rope, k_half, k_rope, cosT, sinT, Qh, Ql, Kh, Kl);

    // HMMA flash attention
    dim3 agrid(S_LEN / 64, NH, B_SZ);
    fattn_kernel<<<agrid, 128, A_SMEM>>>(Qh, Ql, Kh, Kl, Vth, Vtl, Y);

    // Y -> bf16 split, output projection
    aconv_kernel<<<(M_TOT * HIDDEN / 4 + 255) / 256, 256>>>(Y, xbh, xbl, M_TOT * HIDDEN / 4);
    launch_mma(xbh, xbl, wbh + OFF_O, wbl + OFF_O, out, M_TOT, 2048, 2048);
}

// round 7
// speedup vs baseline: 1.5195x; 1.5195x over previous
#include <cuda_runtime.h>
#include <cuda_bf16.h>
#include <cstdint>
#include <math.h>

#define S_LEN   2048
#define B_SZ    2
#define NH      16
#define HD      128
#define M_TOT   (B_SZ * S_LEN)     /* 4096 */
#define HIDDEN  2048
#define LATENT  512

// ---------------- scratch (device globals: no allocation allowed) ----------------
__device__ float g_kv_lat[M_TOT * LATENT];
__device__ float g_q_lat [M_TOT * LATENT];
__device__ float g_k_half[M_TOT * (NH * 64)];
__device__ float g_q_half[M_TOT * (NH * 64)];
__device__ float g_k_rope[M_TOT * (NH * 64)];
__device__ float g_q_rope[M_TOT * (NH * 64)];
__device__ float g_v     [M_TOT * HIDDEN];
__device__ float g_y     [M_TOT * HIDDEN];
__device__ float g_cos   [S_LEN * 32];
__device__ float g_sin   [S_LEN * 32];

// bf16 hi/lo split buffers
__device__ __nv_bfloat16 g_xb_hi[M_TOT * HIDDEN];   // also reused for Y
__device__ __nv_bfloat16 g_xb_lo[M_TOT * HIDDEN];
__device__ __nv_bfloat16 g_kvb_hi[M_TOT * LATENT];
__device__ __nv_bfloat16 g_kvb_lo[M_TOT * LATENT];
__device__ __nv_bfloat16 g_qb_hi[M_TOT * LATENT];
__device__ __nv_bfloat16 g_qb_lo[M_TOT * LATENT];

// attention operands (bf16 hi/lo)
__device__ __nv_bfloat16 g_Qh[M_TOT * HIDDEN];
__device__ __nv_bfloat16 g_Ql[M_TOT * HIDDEN];
__device__ __nv_bfloat16 g_Kh[M_TOT * HIDDEN];
__device__ __nv_bfloat16 g_Kl[M_TOT * HIDDEN];
__device__ __nv_bfloat16 g_Vth[B_SZ * NH * HD * S_LEN];  // [b][h][d][s]
__device__ __nv_bfloat16 g_Vtl[B_SZ * NH * HD * S_LEN];

// transposed weights [N,K] bf16 hi/lo, one pool with offsets
#define OFF_KV_D   0
#define OFF_Q_D    1048576
#define OFF_ROPE_K 2097152
#define OFF_K_U    4194304
#define OFF_Q_U    4718592
#define OFF_ROPE_Q 5242880
#define OFF_V_U    5767168
#define OFF_O      6815744
#define W_POOL     11010048
__device__ __nv_bfloat16 g_wb_hi[W_POOL];
__device__ __nv_bfloat16 g_wb_lo[W_POOL];

// ================= helpers =================
__device__ __forceinline__ uint32_t smem_u32(const void* p) {
    uint32_t a;
    asm("{ .reg .u64 t; cvta.to.shared.u64 t, %1; cvt.u32.u64 %0, t; }" : "=r"(a) : "l"(p));
    return a;
}

__device__ __forceinline__ void ldmx4(uint32_t* r, uint32_t addr) {
    asm volatile("ldmatrix.sync.aligned.m8n8.x4.shared.b16 {%0,%1,%2,%3}, [%4];"
        : "=r"(r[0]), "=r"(r[1]), "=r"(r[2]), "=r"(r[3]) : "r"(addr));
}

__device__ __forceinline__ void mma16816(float* c, const uint32_t* a, uint32_t b0, uint32_t b1) {
    asm volatile(
        "mma.sync.aligned.m16n8k16.row.col.f32.bf16.bf16.f32 "
        "{%0,%1,%2,%3}, {%4,%5,%6,%7}, {%8,%9}, {%0,%1,%2,%3};"
        : "+f"(c[0]), "+f"(c[1]), "+f"(c[2]), "+f"(c[3])
        : "r"(a[0]), "r"(a[1]), "r"(a[2]), "r"(a[3]), "r"(b0), "r"(b1));
}

__device__ __forceinline__ void cp16(uint32_t dst, const void* src) {
    unsigned long long g = (unsigned long long)__cvta_generic_to_global(src);
    asm volatile("cp.async.cg.shared.global [%0], [%1], 16;" :: "r"(dst), "l"(g) : "memory");
}

__device__ __forceinline__ void bsplit2(float a, float b, uint32_t& hi, uint32_t& lo) {
    __nv_bfloat162 h, l;
    h.x = __float2bfloat16(a); l.x = __float2bfloat16(a - __bfloat162float(h.x));
    h.y = __float2bfloat16(b); l.y = __float2bfloat16(b - __bfloat162float(h.y));
    hi = *(uint32_t*)&h; lo = *(uint32_t*)&l;
}

// ================= conversion kernels =================
__global__ __launch_bounds__(256) void aconv_kernel(
    const float* __restrict__ A, __nv_bfloat16* __restrict__ hi,
    __nv_bfloat16* __restrict__ lo, int n4)
{
    int i = blockIdx.x * 256 + threadIdx.x;
    if (i >= n4) return;
    float4 v = ((const float4*)A)[i];
    __nv_bfloat162 h01, h23, l01, l23;
    h01.x = __float2bfloat16(v.x); l01.x = __float2bfloat16(v.x - __bfloat162float(h01.x));
    h01.y = __float2bfloat16(v.y); l01.y = __float2bfloat16(v.y - __bfloat162float(h01.y));
    h23.x = __float2bfloat16(v.z); l23.x = __float2bfloat16(v.z - __bfloat162float(h23.x));
    h23.y = __float2bfloat16(v.w); l23.y = __float2bfloat16(v.w - __bfloat162float(h23.y));
    uint2 hv, lv;
    hv.x = *(uint32_t*)&h01; hv.y = *(uint32_t*)&h23;
    lv.x = *(uint32_t*)&l01; lv.y = *(uint32_t*)&l23;
    ((uint2*)hi)[i] = hv;
    ((uint2*)lo)[i] = lv;
}

// W[K][N] fp32 -> Wt[N][K] bf16 hi/lo (transpose via smem tile)
__global__ void wconv_kernel(const float* __restrict__ W, __nv_bfloat16* __restrict__ hi,
                             __nv_bfloat16* __restrict__ lo, int K, int N)
{
    __shared__ float t[32][33];
    int n0 = blockIdx.x * 32, k0 = blockIdx.y * 32;
    int tx = threadIdx.x, ty = threadIdx.y;
    for (int j = ty; j < 32; j += 8)
        t[j][tx] = W[(size_t)(k0 + j) * N + n0 + tx];
    __syncthreads();
    for (int j = ty; j < 32; j += 8) {
        float v = t[tx][j];
        __nv_bfloat16 h = __float2bfloat16(v);
        size_t o = (size_t)(n0 + j) * K + k0 + tx;
        hi[o] = h;
        lo[o] = __float2bfloat16(v - __bfloat162float(h));
    }
}

// V fp32 [b*S+s][h*128+d] -> Vt bf16 hi/lo [(b*16+h)*128+d][s]
__global__ void vtconv_kernel(const float* __restrict__ V,
                              __nv_bfloat16* __restrict__ Vh, __nv_bfloat16* __restrict__ Vl)
{
    __shared__ float t[32][33];
    int bh_ = blockIdx.z;
    int b = bh_ >> 4, h = bh_ & 15;
    int s0 = blockIdx.x * 32, d0 = blockIdx.y * 32;
    int tx = threadIdx.x, ty = threadIdx.y;
    for (int j = ty; j < 32; j += 8)
        t[j][tx] = V[(size_t)(b * S_LEN + s0 + j) * HIDDEN + h * HD + d0 + tx];
    __syncthreads();
    for (int j = ty; j < 32; j += 8) {
        float v = t[tx][j];   // V[s0+tx][d0+j]
        __nv_bfloat16 hh = __float2bfloat16(v);
        size_t o = ((size_t)bh_ * HD + d0 + j) * S_LEN + s0 + tx;
        Vh[o] = hh;
        Vl[o] = __float2bfloat16(v - __bfloat162float(hh));
    }
}

// ================= HMMA split-bf16 GEMM (proven in R4) =================
#define G_STAGE 32768
#define G_SMEM  (3 * G_STAGE)

__device__ __forceinline__ void gemm_load_chunk(
    uint32_t stage, int tid,
    const __nv_bfloat16* Ahi, const __nv_bfloat16* Alo,
    const __nv_bfloat16* Bhi, const __nv_bfloat16* Blo,
    int m0, int n0, int kc, int K)
{
#pragma unroll
    for (int i = 0; i < 8; i++) {
        int f = i * 256 + tid;
        int t = f >> 9;
        int r = (f >> 2) & 127;
        int u = f & 3;
        const __nv_bfloat16* bp = (t == 0) ? Ahi : (t == 1) ? Alo : (t == 2) ? Bhi : Blo;
        int row = ((t < 2) ? m0 : n0) + r;
        const __nv_bfloat16* src = bp + (size_t)row * K + kc + u * 8;
        uint32_t dst = stage + t * 8192 + r * 64 + ((u ^ ((r >> 1) & 3)) * 16);
        cp16(dst, src);
    }
    asm volatile("cp.async.commit_group;" ::: "memory");
}

__global__ __launch_bounds__(256) void hmma_gemm_kernel(
    const __nv_bfloat16* __restrict__ Ahi, const __nv_bfloat16* __restrict__ Alo,
    const __nv_bfloat16* __restrict__ Bhi, const __nv_bfloat16* __restrict__ Blo,
    float* __restrict__ C, int M, int N, int K)
{
    extern __shared__ __align__(128) char smem[];
    uint32_t sb = smem_u32(smem);
    const int tid = threadIdx.x, lane = tid & 31, wid = tid >> 5;
    const int wm = wid >> 2, wn = wid & 3;
    const int m0 = blockIdx.y << 7, n0 = blockIdx.x << 7;
    const int q = lane >> 3, rr = lane & 7;

    uint32_t offA[4][2], offB[2][2];
#pragma unroll
    for (int mi = 0; mi < 4; mi++)
#pragma unroll
        for (int ks = 0; ks < 2; ks++) {
            int row = wm * 64 + mi * 16 + (q & 1) * 8 + rr;
            int u = ks * 2 + (q >> 1);
            offA[mi][ks] = row * 64 + ((u ^ ((row >> 1) & 3)) * 16);
        }
#pragma unroll
    for (int n2 = 0; n2 < 2; n2++)
#pragma unroll
        for (int ks = 0; ks < 2; ks++) {
            int row = wn * 32 + n2 * 16 + (q >> 1) * 8 + rr;
            int u = ks * 2 + (q & 1);
            offB[n2][ks] = row * 64 + ((u ^ ((row >> 1) & 3)) * 16);
        }

    float acc[4][4][4];
#pragma unroll
    for (int a = 0; a < 4; a++)
#pragma unroll
        for (int b = 0; b < 4; b++)
#pragma unroll
            for (int cc = 0; cc < 4; cc++) acc[a][b][cc] = 0.0f;

    const int NC = K >> 5;

    gemm_load_chunk(sb,           tid, Ahi, Alo, Bhi, Blo, m0, n0, 0,  K);
    gemm_load_chunk(sb + G_STAGE, tid, Ahi, Alo, Bhi, Blo, m0, n0, 32, K);

    int sidx = 0;
    for (int c = 0; c < NC; c++) {
        if (c + 1 < NC) asm volatile("cp.async.wait_group 1;" ::: "memory");
        else            asm volatile("cp.async.wait_group 0;" ::: "memory");
        __syncthreads();

        if (c + 2 < NC) {
            int s2 = sidx + 2; if (s2 >= 3) s2 -= 3;
            gemm_load_chunk(sb + s2 * G_STAGE, tid, Ahi, Alo, Bhi, Blo,
                            m0, n0, (c + 2) << 5, K);
        }

        const uint32_t stage = sb + sidx * G_STAGE;
#pragma unroll
        for (int ks = 0; ks < 2; ks++) {
            uint32_t ah[4][4], al[4][4], bh[2][4], bl[2][4];
#pragma unroll
            for (int mi = 0; mi < 4; mi++) ldmx4(ah[mi], stage + offA[mi][ks]);
#pragma unroll
            for (int mi = 0; mi < 4; mi++) ldmx4(al[mi], stage + 8192 + offA[mi][ks]);
#pragma unroll
            for (int n2 = 0; n2 < 2; n2++) ldmx4(bh[n2], stage + 16384 + offB[n2][ks]);
#pragma unroll
            for (int n2 = 0; n2 < 2; n2++) ldmx4(bl[n2], stage + 24576 + offB[n2][ks]);
#pragma unroll
            for (int mi = 0; mi < 4; mi++) {
#pragma unroll
                for (int ni = 0; ni < 4; ni++) {
                    const int n2 = ni >> 1, hf = ni & 1;
                    mma16816(acc[mi][ni], ah[mi], bh[n2][hf * 2], bh[n2][hf * 2 + 1]);
                    mma16816(acc[mi][ni], ah[mi], bl[n2][hf * 2], bl[n2][hf * 2 + 1]);
                    mma16816(acc[mi][ni], al[mi], bh[n2][hf * 2], bh[n2][hf * 2 + 1]);
                }
            }
        }
        __syncthreads();
        sidx++; if (sidx == 3) sidx = 0;
    }

    const int cm = m0 + wm * 64 + (lane >> 2);
    const int cn = n0 + wn * 32 + (lane & 3) * 2;
#pragma unroll
    for (int mi = 0; mi < 4; mi++) {
#pragma unroll
        for (int ni = 0; ni < 4; ni++) {
            float* p0 = C + (size_t)(cm + mi * 16)     * N + cn + ni * 8;
            float* p1 = C + (size_t)(cm + mi * 16 + 8) * N + cn + ni * 8;
            *(float2*)p0 = make_float2(acc[mi][ni][0], acc[mi][ni][1]);
            *(float2*)p1 = make_float2(acc[mi][ni][2], acc[mi][ni][3]);
        }
    }
}

// ---------------- RoPE cos/sin table ----------------
__global__ void rope_table_kernel(float* __restrict__ cosT, float* __restrict__ sinT) {
    int idx = blockIdx.x * blockDim.x + threadIdx.x;
    if (idx >= S_LEN * 32) return;
    int s = idx >> 5;
    int i = idx & 31;
    double inv = exp(-((double)i / 32.0) * log(10000.0));
    double a   = (double)s * inv;
    cosT[idx] = (float)cos(a);
    sinT[idx] = (float)sin(a);
}

// ---------------- assemble q/k (RoPE) -> bf16 hi/lo, Q prescaled ----------------
__global__ __launch_bounds__(256) void assemble_qk_kernel(
    const float* __restrict__ qh, const float* __restrict__ qr,
    const float* __restrict__ kh, const float* __restrict__ kr,
    const float* __restrict__ cosT, const float* __restrict__ sinT,
    __nv_bfloat16* __restrict__ Qh, __nv_bfloat16* __restrict__ Ql,
    __nv_bfloat16* __restrict__ Kh, __nv_bfloat16* __restrict__ Kl)
{
    const float scale = 0.08838834764831845f;   // 1/sqrt(128)
    int idx = blockIdx.x * blockDim.x + threadIdx.x;
    if (idx >= M_TOT * 1024) return;
    int row = idx >> 10;
    int hj  = idx & 1023;
    int h = hj >> 6;
    int j = hj & 63;
    int s = row & (S_LEN - 1);

    size_t o0 = (size_t)row * HIDDEN + h * HD + j;
    size_t o1 = o0 + 64;

    float qn = qh[idx] * scale;
    float kn = kh[idx];
    __nv_bfloat16 t;
    t = __float2bfloat16(qn); Qh[o0] = t; Ql[o0] = __float2bfloat16(qn - __bfloat162float(t));
    t = __float2bfloat16(kn); Kh[o0] = t; Kl[o0] = __float2bfloat16(kn - __bfloat162float(t));

    int fi = j & 31;
    float c  = cosT[s * 32 + fi];
    float sn = sinT[s * 32 + fi];
    int pair = (j < 32) ? idx + 32 : idx - 32;
    float sgn = (j < 32) ? -1.0f : 1.0f;
    float qv = (qr[idx] * c + sgn * qr[pair] * sn) * scale;
    float kv =  kr[idx] * c + sgn * kr[pair] * sn;
    t = __float2bfloat16(qv); Qh[o1] = t; Ql[o1] = __float2bfloat16(qv - __bfloat162float(t));
    t = __float2bfloat16(kv); Kh[o1] = t; Kl[o1] = __float2bfloat16(kv - __bfloat162float(t));
}

// ================= HMMA flash attention =================
// CTA: 64 q-rows x one (b,h); 4 warps, each 16 q-rows. K-tile = 64 keys.
// Smem: Qhi|Qlo (16KB each) + 2 stages x (Khi|Klo|Vthi|Vtlo) (16KB each) = 160KB.
#define A_SMEM (32768 + 2 * 65536)

__device__ __forceinline__ void attn_load_tile(
    uint32_t stg, int tid, int b, int h, int k0,
    const __nv_bfloat16* Kh, const __nv_bfloat16* Kl,
    const __nv_bfloat16* Vh, const __nv_bfloat16* Vl)
{
#pragma unroll
    for (int i = 0; i < 32; i++) {
        int f = i * 128 + tid;
        int t = f >> 10;       // 0:Kh 1:Kl 2:Vh 3:Vl
        int g = f & 1023;
        if (t < 2) {
            int r = g >> 4, u = g & 15;
            const __nv_bfloat16* src = ((t == 0) ? Kh : Kl)
                + (size_t)(b * S_LEN + k0 + r) * HIDDEN + h * HD + u * 8;
            cp16(stg + t * 16384 + r * 256 + ((u ^ (r & 7)) << 4), src);
        } else {
            int d = g >> 3, u = g & 7;
            const __nv_bfloat16* src = ((t == 2) ? Vh : Vl)
                + ((size_t)(b * NH + h) * HD + d) * S_LEN + k0 + u * 8;
            cp16(stg + t * 16384 + d * 128 + ((u ^ (d & 7)) << 4), src);
        }
    }
    asm volatile("cp.async.commit_group;" ::: "memory");
}

__global__ __launch_bounds__(128) void fattn_kernel(
    const __nv_bfloat16* __restrict__ Qh, const __nv_bfloat16* __restrict__ Ql,
    const __nv_bfloat16* __restrict__ Kh, const __nv_bfloat16* __restrict__ Kl,
    const __nv_bfloat16* __restrict__ Vth, const __nv_bfloat16* __restrict__ Vtl,
    float* __restrict__ Y)
{
    extern __shared__ __align__(128) char smem[];
    uint32_t sb = smem_u32(smem);
    const int qt = (S_LEN / 64 - 1) - blockIdx.x;   // long rows first
    const int h = blockIdx.y, b = blockIdx.z;
    const int tid = threadIdx.x, lane = tid & 31, wm = tid >> 5;
    const int q0 = qt * 64;
    const int rr = lane & 7, qq = lane >> 3;
    const int qb0 = qq >> 1, qb1 = qq & 1;

    // load Q tiles (hi+lo)
#pragma unroll
    for (int i = 0; i < 16; i++) {
        int f = i * 128 + tid;
        int t = f >> 10;
        int g = f & 1023;
        int r = g >> 4, u = g & 15;
        const __nv_bfloat16* src = ((t == 0) ? Qh : Ql)
            + (size_t)(b * S_LEN + q0 + r) * HIDDEN + h * HD + u * 8;
        cp16(sb + t * 16384 + r * 256 + ((u ^ (r & 7)) << 4), src);
    }
    asm volatile("cp.async.commit_group;" ::: "memory");

    attn_load_tile(sb + 32768,         tid, b, h, 0,  Kh, Kl, Vth, Vtl);
    if (qt >= 1) attn_load_tile(sb + 32768 + 65536, tid, b, h, 64, Kh, Kl, Vth, Vtl);

    float o[16][4];
#pragma unroll
    for (int j = 0; j < 16; j++)
#pragma unroll
        for (int e = 0; e < 4; e++) o[j][e] = 0.0f;
    float m0 = -1e30f, m1 = -1e30f, l0 = 0.0f, l1 = 0.0f;

    // precomputable pieces
    const int rA = wm * 16 + qb1 * 8 + rr;              // q-row within tile (A frag)
    const uint32_t offQbase = rA * 256;
    const int swA = rA & 7;

    for (int kt = 0; kt <= qt; kt++) {
        if (kt < qt) asm volatile("cp.async.wait_group 1;" ::: "memory");
        else         asm volatile("cp.async.wait_group 0;" ::: "memory");
        __syncthreads();

        const uint32_t stg = sb + 32768 + (kt & 1) * 65536;
        const int k0 = kt * 64;

        // ---- S = Q K^T (3-term split) ----
        float s[8][4];
#pragma unroll
        for (int j = 0; j < 8; j++)
#pragma unroll
            for (int e = 0; e < 4; e++) s[j][e] = 0.0f;

#pragma unroll
        for (int ks = 0; ks < 8; ks++) {
            uint32_t ah[4], al[4];
            uint32_t ua = 2 * ks + qb0;
            uint32_t qoff = offQbase + ((ua ^ swA) << 4);
            ldmx4(ah, sb + qoff);
            ldmx4(al, sb + 16384 + qoff);
#pragma unroll
            for (int n2 = 0; n2 < 4; n2++) {
                int rB = n2 * 16 + qb0 * 8 + rr;
                uint32_t ub = 2 * ks + qb1;
                uint32_t koff = rB * 256 + (((ub ^ (rB & 7))) << 4);
                uint32_t bh[4], bl[4];
                ldmx4(bh, stg + koff);
                ldmx4(bl, stg + 16384 + koff);
                mma16816(s[2 * n2],     ah, bh[0], bh[1]);
                mma16816(s[2 * n2],     ah, bl[0], bl[1]);
                mma16816(s[2 * n2],     al, bh[0], bh[1]);
                mma16816(s[2 * n2 + 1], ah, bh[2], bh[3]);
                mma16816(s[2 * n2 + 1], ah, bl[2], bl[3]);
                mma16816(s[2 * n2 + 1], al, bh[2], bh[3]);
            }
        }

        // ---- causal mask (diagonal tile only) ----
        if (kt == qt) {
            int rbase = q0 + wm * 16 + (lane >> 2);
            int cbase = k0 + (lane & 3) * 2;
#pragma unroll
            for (int j = 0; j < 8; j++) {
                int c0 = cbase + j * 8, c1 = c0 + 1;
                if (c0 > rbase)     s[j][0] = -1e30f;
                if (c1 > rbase)     s[j][1] = -1e30f;
                if (c0 > rbase + 8) s[j][2] = -1e30f;
                if (c1 > rbase + 8) s[j][3] = -1e30f;
            }
        }

        // ---- online softmax ----
        float mt0 = -1e30f, mt1 = -1e30f;
#pragma unroll
        for (int j = 0; j < 8; j++) {
            mt0 = fmaxf(mt0, fmaxf(s[j][0], s[j][1]));
            mt1 = fmaxf(mt1, fmaxf(s[j][2], s[j][3]));
        }
        mt0 = fmaxf(mt0, __shfl_xor_sync(0xffffffffu, mt0, 1));
        mt0 = fmaxf(mt0, __shfl_xor_sync(0xffffffffu, mt0, 2));
        mt1 = fmaxf(mt1, __shfl_xor_sync(0xffffffffu, mt1, 1));
        mt1 = fmaxf(mt1, __shfl_xor_sync(0xffffffffu, mt1, 2));
        float mn0 = fmaxf(m0, mt0), mn1 = fmaxf(m1, mt1);
        float cr0 = __expf(m0 - mn0), cr1 = __expf(m1 - mn1);
        m0 = mn0; m1 = mn1;

        float ps0 = 0.0f, ps1 = 0.0f;
#pragma unroll
        for (int j = 0; j < 8; j++) {
            s[j][0] = __expf(s[j][0] - mn0);
            s[j][1] = __expf(s[j][1] - mn0);
            s[j][2] = __expf(s[j][2] - mn1);
            s[j][3] = __expf(s[j][3] - mn1);
            ps0 += s[j][0] + s[j][1];
            ps1 += s[j][2] + s[j][3];
        }
        ps0 += __shfl_xor_sync(0xffffffffu, ps0, 1);
        ps0 += __shfl_xor_sync(0xffffffffu, ps0, 2);
        ps1 += __shfl_xor_sync(0xffffffffu, ps1, 1);
        ps1 += __shfl_xor_sync(0xffffffffu, ps1, 2);
        l0 = l0 * cr0 + ps0;
        l1 = l1 * cr1 + ps1;
#pragma unroll
        for (int j = 0; j < 16; j++) {
            o[j][0] *= cr0; o[j][1] *= cr0;
            o[j][2] *= cr1; o[j][3] *= cr1;
        }

        // ---- P -> bf16 hi/lo A-fragments ----
        uint32_t phi[4][4], plo[4][4];
#pragma unroll
        for (int ks = 0; ks < 4; ks++) {
            bsplit2(s[2 * ks][0],     s[2 * ks][1],     phi[ks][0], plo[ks][0]);
            bsplit2(s[2 * ks][2],     s[2 * ks][3],     phi[ks][1], plo[ks][1]);
            bsplit2(s[2 * ks + 1][0], s[2 * ks + 1][1], phi[ks][2], plo[ks][2]);
            bsplit2(s[2 * ks + 1][2], s[2 * ks + 1][3], phi[ks][3], plo[ks][3]);
        }

        // ---- O += P @ V (3-term split), B = Vt tiles ----
#pragma unroll
        for (int v2 = 0; v2 < 8; v2++) {
            int rv = v2 * 16 + qb0 * 8 + rr;
            uint32_t vbase = stg + 32768 + rv * 128;
            int swv = rv & 7;
#pragma unroll
            for (int ks = 0; ks < 4; ks++) {
                uint32_t u = 2 * ks + qb1;
                uint32_t voff = (u ^ swv) << 4;
                uint32_t bh[4], bl[4];
                ldmx4(bh, vbase + voff);
                ldmx4(bl, vbase + 16384 + voff);
                float* o0 = o[v2 * 2];
                float* o1 = o[v2 * 2 + 1];
                mma16816(o0, phi[ks], bh[0], bh[1]);
                mma16816(o0, phi[ks], bl[0], bl[1]);
                mma16816(o0, plo[ks], bh[0], bh[1]);
                mma16816(o1, phi[ks], bh[2], bh[3]);
                mma16816(o1, phi[ks], bl[2], bl[3]);
                mma16816(o1, plo[ks], bh[2], bh[3]);
            }
        }

        if (kt + 2 <= qt) {
            __syncthreads();
            attn_load_tile(sb + 32768 + (kt & 1) * 65536, tid, b, h, (kt + 2) * 64,
                           Kh, Kl, Vth, Vtl);
        }
    }

    // ---- epilogue ----
    float inv0 = 1.0f / l0, inv1 = 1.0f / l1;
    int row0 = b * S_LEN + q0 + wm * 16 + (lane >> 2);
    int colb = h * HD + (lane & 3) * 2;
#pragma unroll
    for (int j = 0; j < 16; j++) {
        *(float2*)(Y + (size_t)row0 * HIDDEN + colb + j * 8)
            = make_float2(o[j][0] * inv0, o[j][1] * inv0);
        *(float2*)(Y + (size_t)(row0 + 8) * HIDDEN + colb + j * 8)
            = make_float2(o[j][2] * inv1, o[j][3] * inv1);
    }
}

// ---------------- host ----------------
static void launch_mma(const __nv_bfloat16* Ah, const __nv_bfloat16* Al,
                       const __nv_bfloat16* Bh, const __nv_bfloat16* Bl,
                       float* C, int M, int N, int K)
{
    dim3 grid(N / 128, M / 128);
    hmma_gemm_kernel<<<grid, 256, G_SMEM>>>(Ah, Al, Bh, Bl, C, M, N, K);
}

extern "C" void kernel_launch(void* const* d_in, const int* in_sizes, int n_in,
                              void* d_out, int out_size)
{
    const float* x        = (const float*)d_in[0];
    const float* W_kv_d   = (const float*)d_in[1];
    const float* W_q_d    = (const float*)d_in[2];
    const float* W_k_u    = (const float*)d_in[3];
    const float* W_q_u    = (const float*)d_in[4];
    const float* W_v_u    = (const float*)d_in[5];
    const float* W_rope_k = (const float*)d_in[6];
    const float* W_rope_q = (const float*)d_in[7];
    const float* W_o      = (const float*)d_in[8];
    float* out = (float*)d_out;

    float *kv_lat, *q_lat, *k_half, *q_half, *k_rope, *q_rope, *V, *Y, *cosT, *sinT;
    __nv_bfloat16 *xbh, *xbl, *kvbh, *kvbl, *qbh, *qbl, *wbh, *wbl;
    __nv_bfloat16 *Qh, *Ql, *Kh, *Kl, *Vth, *Vtl;
    cudaGetSymbolAddress((void**)&kv_lat, g_kv_lat);
    cudaGetSymbolAddress((void**)&q_lat,  g_q_lat);
    cudaGetSymbolAddress((void**)&k_half, g_k_half);
    cudaGetSymbolAddress((void**)&q_half, g_q_half);
    cudaGetSymbolAddress((void**)&k_rope, g_k_rope);
    cudaGetSymbolAddress((void**)&q_rope, g_q_rope);
    cudaGetSymbolAddress((void**)&V,      g_v);
    cudaGetSymbolAddress((void**)&Y,      g_y);
    cudaGetSymbolAddress((void**)&cosT,   g_cos);
    cudaGetSymbolAddress((void**)&sinT,   g_sin);
    cudaGetSymbolAddress((void**)&xbh,    g_xb_hi);
    cudaGetSymbolAddress((void**)&xbl,    g_xb_lo);
    cudaGetSymbolAddress((void**)&kvbh,   g_kvb_hi);
    cudaGetSymbolAddress((void**)&kvbl,   g_kvb_lo);
    cudaGetSymbolAddress((void**)&qbh,    g_qb_hi);
    cudaGetSymbolAddress((void**)&qbl,    g_qb_lo);
    cudaGetSymbolAddress((void**)&wbh,    g_wb_hi);
    cudaGetSymbolAddress((void**)&wbl,    g_wb_lo);
    cudaGetSymbolAddress((void**)&Qh,     g_Qh);
    cudaGetSymbolAddress((void**)&Ql,     g_Ql);
    cudaGetSymbolAddress((void**)&Kh,     g_Kh);
    cudaGetSymbolAddress((void**)&Kl,     g_Kl);
    cudaGetSymbolAddress((void**)&Vth,    g_Vth);
    cudaGetSymbolAddress((void**)&Vtl,    g_Vtl);

    cudaFuncSetAttribute(hmma_gemm_kernel, cudaFuncAttributeMaxDynamicSharedMemorySize, G_SMEM);
    cudaFuncSetAttribute(fattn_kernel, cudaFuncAttributeMaxDynamicSharedMemorySize, A_SMEM);

    rope_table_kernel<<<(S_LEN * 32 + 255) / 256, 256>>>(cosT, sinT);

    // weight conversions (fp32 [K,N] -> bf16 hi/lo [N,K])
    dim3 wb(32, 8);
    wconv_kernel<<<dim3( 512/32, 2048/32), wb>>>(W_kv_d,   wbh + OFF_KV_D,   wbl + OFF_KV_D,   2048,  512);
    wconv_kernel<<<dim3( 512/32, 2048/32), wb>>>(W_q_d,    wbh + OFF_Q_D,    wbl + OFF_Q_D,    2048,  512);
    wconv_kernel<<<dim3(1024/32, 2048/32), wb>>>(W_rope_k, wbh + OFF_ROPE_K, wbl + OFF_ROPE_K, 2048, 1024);
    wconv_kernel<<<dim3(1024/32,  512/32), wb>>>(W_k_u,    wbh + OFF_K_U,    wbl + OFF_K_U,     512, 1024);
    wconv_kernel<<<dim3(1024/32,  512/32), wb>>>(W_q_u,    wbh + OFF_Q_U,    wbl + OFF_Q_U,     512, 1024);
    wconv_kernel<<<dim3(1024/32,  512/32), wb>>>(W_rope_q, wbh + OFF_ROPE_Q, wbl + OFF_ROPE_Q,  512, 1024);
    wconv_kernel<<<dim3(2048/32,  512/32), wb>>>(W_v_u,    wbh + OFF_V_U,    wbl + OFF_V_U,     512, 2048);
    wconv_kernel<<<dim3(2048/32, 2048/32), wb>>>(W_o,      wbh + OFF_O,      wbl + OFF_O,      2048, 2048);

    // x -> bf16 split
    aconv_kernel<<<(M_TOT * HIDDEN / 4 + 255) / 256, 256>>>(x, xbh, xbl, M_TOT * HIDDEN / 4);

    // level 1 GEMMs (K=2048)
    launch_mma(xbh, xbl, wbh + OFF_KV_D,   wbl + OFF_KV_D,   kv_lat, M_TOT,  512, 2048);
    launch_mma(xbh, xbl, wbh + OFF_Q_D,    wbl + OFF_Q_D,    q_lat,  M_TOT,  512, 2048);
    launch_mma(xbh, xbl, wbh + OFF_ROPE_K, wbl + OFF_ROPE_K, k_rope, M_TOT, 1024, 2048);

    // latents -> bf16 split
    aconv_kernel<<<(M_TOT * LATENT / 4 + 255) / 256, 256>>>(kv_lat, kvbh, kvbl, M_TOT * LATENT / 4);
    aconv_kernel<<<(M_TOT * LATENT / 4 + 255) / 256, 256>>>(q_lat,  qbh,  qbl,  M_TOT * LATENT / 4);

    // level 2 GEMMs (K=512)
    launch_mma(kvbh, kvbl, wbh + OFF_K_U,    wbl + OFF_K_U,    k_half, M_TOT, 1024, 512);
    launch_mma(qbh,  qbl,  wbh + OFF_Q_U,    wbl + OFF_Q_U,    q_half, M_TOT, 1024, 512);
    launch_mma(qbh,  qbl,  wbh + OFF_ROPE_Q, wbl + OFF_ROPE_Q, q_rope, M_TOT, 1024, 512);
    launch_mma(kvbh, kvbl, wbh + OFF_V_U,    wbl + OFF_V_U,    V,      M_TOT, 2048, 512);

    // V -> Vt bf16 hi/lo; q/k assemble -> bf16 hi/lo (Q prescaled)
    vtconv_kernel<<<dim3(S_LEN / 32, HD / 32, B_SZ * NH), wb>>>(V, Vth, Vtl);
    assemble_qk_kernel<<<(M_TOT * 1024 + 255) / 256, 256>>>(
        q_half, q_rope, k_half, k_rope, cosT, sinT, Qh, Ql, Kh, Kl);

    // HMMA flash attention
    dim3 agrid(S_LEN / 64, NH, B_SZ);
    fattn_kernel<<<agrid, 128, A_SMEM>>>(Qh, Ql, Kh, Kl, Vth, Vtl, Y);

    // Y -> bf16 split, output projection
    aconv_kernel<<<(M_TOT * HIDDEN / 4 + 255) / 256, 256>>>(Y, xbh, xbl, M_TOT * HIDDEN / 4);
    launch_mma(xbh, xbl, wbh + OFF_O, wbl + OFF_O, out, M_TOT, 2048, 2048);
}

// round 8
// speedup vs baseline: 1.5233x; 1.0025x over previous
#include <cuda_runtime.h>
#include <cuda_bf16.h>
#include <cstdint>
#include <math.h>

#define S_LEN   2048
#define B_SZ    2
#define NH      16
#define HD      128
#define M_TOT   (B_SZ * S_LEN)     /* 4096 */
#define HIDDEN  2048
#define LATENT  512

// ---------------- scratch (device globals: no allocation allowed) ----------------
__device__ float g_kv_lat[M_TOT * LATENT];
__device__ float g_q_lat [M_TOT * LATENT];
__device__ float g_k_half[M_TOT * (NH * 64)];
__device__ float g_q_half[M_TOT * (NH * 64)];
__device__ float g_k_rope[M_TOT * (NH * 64)];
__device__ float g_q_rope[M_TOT * (NH * 64)];
__device__ float g_v     [M_TOT * HIDDEN];
__device__ float g_y     [M_TOT * HIDDEN];
__device__ float g_cos   [S_LEN * 32];
__device__ float g_sin   [S_LEN * 32];

// bf16 hi/lo split buffers
__device__ __nv_bfloat16 g_xb_hi[M_TOT * HIDDEN];   // also reused for Y
__device__ __nv_bfloat16 g_xb_lo[M_TOT * HIDDEN];
__device__ __nv_bfloat16 g_kvb_hi[M_TOT * LATENT];
__device__ __nv_bfloat16 g_kvb_lo[M_TOT * LATENT];
__device__ __nv_bfloat16 g_qb_hi[M_TOT * LATENT];
__device__ __nv_bfloat16 g_qb_lo[M_TOT * LATENT];

// attention operands (bf16 hi/lo)
__device__ __nv_bfloat16 g_Qh[M_TOT * HIDDEN];
__device__ __nv_bfloat16 g_Ql[M_TOT * HIDDEN];
__device__ __nv_bfloat16 g_Kh[M_TOT * HIDDEN];
__device__ __nv_bfloat16 g_Kl[M_TOT * HIDDEN];
__device__ __nv_bfloat16 g_Vth[B_SZ * NH * HD * S_LEN];  // [b][h][d][s]
__device__ __nv_bfloat16 g_Vtl[B_SZ * NH * HD * S_LEN];

// transposed weights [N,K] bf16 hi/lo, one pool with offsets
#define OFF_KV_D   0
#define OFF_Q_D    1048576
#define OFF_ROPE_K 2097152
#define OFF_K_U    4194304
#define OFF_Q_U    4718592
#define OFF_ROPE_Q 5242880
#define OFF_V_U    5767168
#define OFF_O      6815744
#define W_POOL     11010048
__device__ __nv_bfloat16 g_wb_hi[W_POOL];
__device__ __nv_bfloat16 g_wb_lo[W_POOL];

// ================= helpers =================
__device__ __forceinline__ uint32_t smem_u32(const void* p) {
    uint32_t a;
    asm("{ .reg .u64 t; cvta.to.shared.u64 t, %1; cvt.u32.u64 %0, t; }" : "=r"(a) : "l"(p));
    return a;
}

__device__ __forceinline__ void ldmx4(uint32_t* r, uint32_t addr) {
    asm volatile("ldmatrix.sync.aligned.m8n8.x4.shared.b16 {%0,%1,%2,%3}, [%4];"
        : "=r"(r[0]), "=r"(r[1]), "=r"(r[2]), "=r"(r[3]) : "r"(addr));
}

__device__ __forceinline__ void mma16816(float* c, const uint32_t* a, uint32_t b0, uint32_t b1) {
    asm volatile(
        "mma.sync.aligned.m16n8k16.row.col.f32.bf16.bf16.f32 "
        "{%0,%1,%2,%3}, {%4,%5,%6,%7}, {%8,%9}, {%0,%1,%2,%3};"
        : "+f"(c[0]), "+f"(c[1]), "+f"(c[2]), "+f"(c[3])
        : "r"(a[0]), "r"(a[1]), "r"(a[2]), "r"(a[3]), "r"(b0), "r"(b1));
}

__device__ __forceinline__ void cp16(uint32_t dst, const void* src) {
    unsigned long long g = (unsigned long long)__cvta_generic_to_global(src);
    asm volatile("cp.async.cg.shared.global [%0], [%1], 16;" :: "r"(dst), "l"(g) : "memory");
}

__device__ __forceinline__ void bsplit2(float a, float b, uint32_t& hi, uint32_t& lo) {
    __nv_bfloat162 h, l;
    h.x = __float2bfloat16(a); l.x = __float2bfloat16(a - __bfloat162float(h.x));
    h.y = __float2bfloat16(b); l.y = __float2bfloat16(b - __bfloat162float(h.y));
    hi = *(uint32_t*)&h; lo = *(uint32_t*)&l;
}

// ================= conversion kernels =================
__global__ __launch_bounds__(256) void aconv_kernel(
    const float* __restrict__ A, __nv_bfloat16* __restrict__ hi,
    __nv_bfloat16* __restrict__ lo, int n4)
{
    int i = blockIdx.x * 256 + threadIdx.x;
    if (i >= n4) return;
    float4 v = ((const float4*)A)[i];
    __nv_bfloat162 h01, h23, l01, l23;
    h01.x = __float2bfloat16(v.x); l01.x = __float2bfloat16(v.x - __bfloat162float(h01.x));
    h01.y = __float2bfloat16(v.y); l01.y = __float2bfloat16(v.y - __bfloat162float(h01.y));
    h23.x = __float2bfloat16(v.z); l23.x = __float2bfloat16(v.z - __bfloat162float(h23.x));
    h23.y = __float2bfloat16(v.w); l23.y = __float2bfloat16(v.w - __bfloat162float(h23.y));
    uint2 hv, lv;
    hv.x = *(uint32_t*)&h01; hv.y = *(uint32_t*)&h23;
    lv.x = *(uint32_t*)&l01; lv.y = *(uint32_t*)&l23;
    ((uint2*)hi)[i] = hv;
    ((uint2*)lo)[i] = lv;
}

// W[K][N] fp32 -> Wt[N][K] bf16 hi/lo (transpose via smem tile)
__global__ void wconv_kernel(const float* __restrict__ W, __nv_bfloat16* __restrict__ hi,
                             __nv_bfloat16* __restrict__ lo, int K, int N)
{
    __shared__ float t[32][33];
    int n0 = blockIdx.x * 32, k0 = blockIdx.y * 32;
    int tx = threadIdx.x, ty = threadIdx.y;
    for (int j = ty; j < 32; j += 8)
        t[j][tx] = W[(size_t)(k0 + j) * N + n0 + tx];
    __syncthreads();
    for (int j = ty; j < 32; j += 8) {
        float v = t[tx][j];
        __nv_bfloat16 h = __float2bfloat16(v);
        size_t o = (size_t)(n0 + j) * K + k0 + tx;
        hi[o] = h;
        lo[o] = __float2bfloat16(v - __bfloat162float(h));
    }
}

// V fp32 [b*S+s][h*128+d] -> Vt bf16 hi/lo [(b*16+h)*128+d][s]
__global__ void vtconv_kernel(const float* __restrict__ V,
                              __nv_bfloat16* __restrict__ Vh, __nv_bfloat16* __restrict__ Vl)
{
    __shared__ float t[32][33];
    int bh_ = blockIdx.z;
    int b = bh_ >> 4, h = bh_ & 15;
    int s0 = blockIdx.x * 32, d0 = blockIdx.y * 32;
    int tx = threadIdx.x, ty = threadIdx.y;
    for (int j = ty; j < 32; j += 8)
        t[j][tx] = V[(size_t)(b * S_LEN + s0 + j) * HIDDEN + h * HD + d0 + tx];
    __syncthreads();
    for (int j = ty; j < 32; j += 8) {
        float v = t[tx][j];   // V[s0+tx][d0+j]
        __nv_bfloat16 hh = __float2bfloat16(v);
        size_t o = ((size_t)bh_ * HD + d0 + j) * S_LEN + s0 + tx;
        Vh[o] = hh;
        Vl[o] = __float2bfloat16(v - __bfloat162float(hh));
    }
}

// ================= HMMA split-bf16 GEMM (proven in R4) =================
#define G_STAGE 32768
#define G_SMEM  (3 * G_STAGE)

__device__ __forceinline__ void gemm_load_chunk(
    uint32_t stage, int tid,
    const __nv_bfloat16* Ahi, const __nv_bfloat16* Alo,
    const __nv_bfloat16* Bhi, const __nv_bfloat16* Blo,
    int m0, int n0, int kc, int K)
{
#pragma unroll
    for (int i = 0; i < 8; i++) {
        int f = i * 256 + tid;
        int t = f >> 9;
        int r = (f >> 2) & 127;
        int u = f & 3;
        const __nv_bfloat16* bp = (t == 0) ? Ahi : (t == 1) ? Alo : (t == 2) ? Bhi : Blo;
        int row = ((t < 2) ? m0 : n0) + r;
        const __nv_bfloat16* src = bp + (size_t)row * K + kc + u * 8;
        uint32_t dst = stage + t * 8192 + r * 64 + ((u ^ ((r >> 1) & 3)) * 16);
        cp16(dst, src);
    }
    asm volatile("cp.async.commit_group;" ::: "memory");
}

__global__ __launch_bounds__(256) void hmma_gemm_kernel(
    const __nv_bfloat16* __restrict__ Ahi, const __nv_bfloat16* __restrict__ Alo,
    const __nv_bfloat16* __restrict__ Bhi, const __nv_bfloat16* __restrict__ Blo,
    float* __restrict__ C, int M, int N, int K)
{
    extern __shared__ __align__(128) char smem[];
    uint32_t sb = smem_u32(smem);
    const int tid = threadIdx.x, lane = tid & 31, wid = tid >> 5;
    const int wm = wid >> 2, wn = wid & 3;
    const int m0 = blockIdx.y << 7, n0 = blockIdx.x << 7;
    const int q = lane >> 3, rr = lane & 7;

    uint32_t offA[4][2], offB[2][2];
#pragma unroll
    for (int mi = 0; mi < 4; mi++)
#pragma unroll
        for (int ks = 0; ks < 2; ks++) {
            int row = wm * 64 + mi * 16 + (q & 1) * 8 + rr;
            int u = ks * 2 + (q >> 1);
            offA[mi][ks] = row * 64 + ((u ^ ((row >> 1) & 3)) * 16);
        }
#pragma unroll
    for (int n2 = 0; n2 < 2; n2++)
#pragma unroll
        for (int ks = 0; ks < 2; ks++) {
            int row = wn * 32 + n2 * 16 + (q >> 1) * 8 + rr;
            int u = ks * 2 + (q & 1);
            offB[n2][ks] = row * 64 + ((u ^ ((row >> 1) & 3)) * 16);
        }

    float acc[4][4][4];
#pragma unroll
    for (int a = 0; a < 4; a++)
#pragma unroll
        for (int b = 0; b < 4; b++)
#pragma unroll
            for (int cc = 0; cc < 4; cc++) acc[a][b][cc] = 0.0f;

    const int NC = K >> 5;

    gemm_load_chunk(sb,           tid, Ahi, Alo, Bhi, Blo, m0, n0, 0,  K);
    gemm_load_chunk(sb + G_STAGE, tid, Ahi, Alo, Bhi, Blo, m0, n0, 32, K);

    int sidx = 0;
    for (int c = 0; c < NC; c++) {
        if (c + 1 < NC) asm volatile("cp.async.wait_group 1;" ::: "memory");
        else            asm volatile("cp.async.wait_group 0;" ::: "memory");
        __syncthreads();

        if (c + 2 < NC) {
            int s2 = sidx + 2; if (s2 >= 3) s2 -= 3;
            gemm_load_chunk(sb + s2 * G_STAGE, tid, Ahi, Alo, Bhi, Blo,
                            m0, n0, (c + 2) << 5, K);
        }

        const uint32_t stage = sb + sidx * G_STAGE;
#pragma unroll
        for (int ks = 0; ks < 2; ks++) {
            uint32_t ah[4][4], al[4][4], bh[2][4], bl[2][4];
#pragma unroll
            for (int mi = 0; mi < 4; mi++) ldmx4(ah[mi], stage + offA[mi][ks]);
#pragma unroll
            for (int mi = 0; mi < 4; mi++) ldmx4(al[mi], stage + 8192 + offA[mi][ks]);
#pragma unroll
            for (int n2 = 0; n2 < 2; n2++) ldmx4(bh[n2], stage + 16384 + offB[n2][ks]);
#pragma unroll
            for (int n2 = 0; n2 < 2; n2++) ldmx4(bl[n2], stage + 24576 + offB[n2][ks]);
#pragma unroll
            for (int mi = 0; mi < 4; mi++) {
#pragma unroll
                for (int ni = 0; ni < 4; ni++) {
                    const int n2 = ni >> 1, hf = ni & 1;
                    mma16816(acc[mi][ni], ah[mi], bh[n2][hf * 2], bh[n2][hf * 2 + 1]);
                    mma16816(acc[mi][ni], ah[mi], bl[n2][hf * 2], bl[n2][hf * 2 + 1]);
                    mma16816(acc[mi][ni], al[mi], bh[n2][hf * 2], bh[n2][hf * 2 + 1]);
                }
            }
        }
        __syncthreads();
        sidx++; if (sidx == 3) sidx = 0;
    }

    const int cm = m0 + wm * 64 + (lane >> 2);
    const int cn = n0 + wn * 32 + (lane & 3) * 2;
#pragma unroll
    for (int mi = 0; mi < 4; mi++) {
#pragma unroll
        for (int ni = 0; ni < 4; ni++) {
            float* p0 = C + (size_t)(cm + mi * 16)     * N + cn + ni * 8;
            float* p1 = C + (size_t)(cm + mi * 16 + 8) * N + cn + ni * 8;
            *(float2*)p0 = make_float2(acc[mi][ni][0], acc[mi][ni][1]);
            *(float2*)p1 = make_float2(acc[mi][ni][2], acc[mi][ni][3]);
        }
    }
}

// ---------------- RoPE cos/sin table ----------------
__global__ void rope_table_kernel(float* __restrict__ cosT, float* __restrict__ sinT) {
    int idx = blockIdx.x * blockDim.x + threadIdx.x;
    if (idx >= S_LEN * 32) return;
    int s = idx >> 5;
    int i = idx & 31;
    double inv = exp(-((double)i / 32.0) * log(10000.0));
    double a   = (double)s * inv;
    cosT[idx] = (float)cos(a);
    sinT[idx] = (float)sin(a);
}

// ---------------- assemble q/k (RoPE) -> bf16 hi/lo, Q prescaled ----------------
__global__ __launch_bounds__(256) void assemble_qk_kernel(
    const float* __restrict__ qh, const float* __restrict__ qr,
    const float* __restrict__ kh, const float* __restrict__ kr,
    const float* __restrict__ cosT, const float* __restrict__ sinT,
    __nv_bfloat16* __restrict__ Qh, __nv_bfloat16* __restrict__ Ql,
    __nv_bfloat16* __restrict__ Kh, __nv_bfloat16* __restrict__ Kl)
{
    const float scale = 0.08838834764831845f;   // 1/sqrt(128)
    int idx = blockIdx.x * blockDim.x + threadIdx.x;
    if (idx >= M_TOT * 1024) return;
    int row = idx >> 10;
    int hj  = idx & 1023;
    int h = hj >> 6;
    int j = hj & 63;
    int s = row & (S_LEN - 1);

    size_t o0 = (size_t)row * HIDDEN + h * HD + j;
    size_t o1 = o0 + 64;

    float qn = qh[idx] * scale;
    float kn = kh[idx];
    __nv_bfloat16 t;
    t = __float2bfloat16(qn); Qh[o0] = t; Ql[o0] = __float2bfloat16(qn - __bfloat162float(t));
    t = __float2bfloat16(kn); Kh[o0] = t; Kl[o0] = __float2bfloat16(kn - __bfloat162float(t));

    int fi = j & 31;
    float c  = cosT[s * 32 + fi];
    float sn = sinT[s * 32 + fi];
    int pair = (j < 32) ? idx + 32 : idx - 32;
    float sgn = (j < 32) ? -1.0f : 1.0f;
    float qv = (qr[idx] * c + sgn * qr[pair] * sn) * scale;
    float kv =  kr[idx] * c + sgn * kr[pair] * sn;
    t = __float2bfloat16(qv); Qh[o1] = t; Ql[o1] = __float2bfloat16(qv - __bfloat162float(t));
    t = __float2bfloat16(kv); Kh[o1] = t; Kl[o1] = __float2bfloat16(kv - __bfloat162float(t));
}

// ================= HMMA flash attention =================
// CTA: 64 q-rows x one (b,h); 4 warps, each 16 q-rows. K-tile = 64 keys.
// Smem: Qhi|Qlo (16KB each) + 2 stages x (Khi|Klo|Vthi|Vtlo) (16KB each) = 160KB.
#define A_SMEM (32768 + 2 * 65536)

__device__ __forceinline__ void attn_load_tile(
    uint32_t stg, int tid, int b, int h, int k0,
    const __nv_bfloat16* Kh, const __nv_bfloat16* Kl,
    const __nv_bfloat16* Vh, const __nv_bfloat16* Vl)
{
#pragma unroll
    for (int i = 0; i < 32; i++) {
        int f = i * 128 + tid;
        int t = f >> 10;       // 0:Kh 1:Kl 2:Vh 3:Vl
        int g = f & 1023;
        if (t < 2) {
            int r = g >> 4, u = g & 15;
            const __nv_bfloat16* src = ((t == 0) ? Kh : Kl)
                + (size_t)(b * S_LEN + k0 + r) * HIDDEN + h * HD + u * 8;
            cp16(stg + t * 16384 + r * 256 + ((u ^ (r & 7)) << 4), src);
        } else {
            int d = g >> 3, u = g & 7;
            const __nv_bfloat16* src = ((t == 2) ? Vh : Vl)
                + ((size_t)(b * NH + h) * HD + d) * S_LEN + k0 + u * 8;
            cp16(stg + t * 16384 + d * 128 + ((u ^ (d & 7)) << 4), src);
        }
    }
    asm volatile("cp.async.commit_group;" ::: "memory");
}

__global__ __launch_bounds__(128) void fattn_kernel(
    const __nv_bfloat16* __restrict__ Qh, const __nv_bfloat16* __restrict__ Ql,
    const __nv_bfloat16* __restrict__ Kh, const __nv_bfloat16* __restrict__ Kl,
    const __nv_bfloat16* __restrict__ Vth, const __nv_bfloat16* __restrict__ Vtl,
    float* __restrict__ Y)
{
    extern __shared__ __align__(128) char smem[];
    uint32_t sb = smem_u32(smem);
    const int qt = (S_LEN / 64 - 1) - blockIdx.x;   // long rows first
    const int h = blockIdx.y, b = blockIdx.z;
    const int tid = threadIdx.x, lane = tid & 31, wm = tid >> 5;
    const int q0 = qt * 64;
    const int rr = lane & 7, qq = lane >> 3;
    const int qb0 = qq >> 1, qb1 = qq & 1;

    // load Q tiles (hi+lo)
#pragma unroll
    for (int i = 0; i < 16; i++) {
        int f = i * 128 + tid;
        int t = f >> 10;
        int g = f & 1023;
        int r = g >> 4, u = g & 15;
        const __nv_bfloat16* src = ((t == 0) ? Qh : Ql)
            + (size_t)(b * S_LEN + q0 + r) * HIDDEN + h * HD + u * 8;
        cp16(sb + t * 16384 + r * 256 + ((u ^ (r & 7)) << 4), src);
    }
    asm volatile("cp.async.commit_group;" ::: "memory");

    attn_load_tile(sb + 32768,         tid, b, h, 0,  Kh, Kl, Vth, Vtl);
    if (qt >= 1) attn_load_tile(sb + 32768 + 65536, tid, b, h, 64, Kh, Kl, Vth, Vtl);

    float o[16][4];
#pragma unroll
    for (int j = 0; j < 16; j++)
#pragma unroll
        for (int e = 0; e < 4; e++) o[j][e] = 0.0f;
    float m0 = -1e30f, m1 = -1e30f, l0 = 0.0f, l1 = 0.0f;

    // precomputable pieces
    const int rA = wm * 16 + qb1 * 8 + rr;              // q-row within tile (A frag)
    const uint32_t offQbase = rA * 256;
    const int swA = rA & 7;

    for (int kt = 0; kt <= qt; kt++) {
        if (kt < qt) asm volatile("cp.async.wait_group 1;" ::: "memory");
        else         asm volatile("cp.async.wait_group 0;" ::: "memory");
        __syncthreads();

        const uint32_t stg = sb + 32768 + (kt & 1) * 65536;
        const int k0 = kt * 64;

        // ---- S = Q K^T (3-term split) ----
        float s[8][4];
#pragma unroll
        for (int j = 0; j < 8; j++)
#pragma unroll
            for (int e = 0; e < 4; e++) s[j][e] = 0.0f;

#pragma unroll
        for (int ks = 0; ks < 8; ks++) {
            uint32_t ah[4], al[4];
            uint32_t ua = 2 * ks + qb0;
            uint32_t qoff = offQbase + ((ua ^ swA) << 4);
            ldmx4(ah, sb + qoff);
            ldmx4(al, sb + 16384 + qoff);
#pragma unroll
            for (int n2 = 0; n2 < 4; n2++) {
                int rB = n2 * 16 + qb0 * 8 + rr;
                uint32_t ub = 2 * ks + qb1;
                uint32_t koff = rB * 256 + (((ub ^ (rB & 7))) << 4);
                uint32_t bh[4], bl[4];
                ldmx4(bh, stg + koff);
                ldmx4(bl, stg + 16384 + koff);
                mma16816(s[2 * n2],     ah, bh[0], bh[1]);
                mma16816(s[2 * n2],     ah, bl[0], bl[1]);
                mma16816(s[2 * n2],     al, bh[0], bh[1]);
                mma16816(s[2 * n2 + 1], ah, bh[2], bh[3]);
                mma16816(s[2 * n2 + 1], ah, bl[2], bl[3]);
                mma16816(s[2 * n2 + 1], al, bh[2], bh[3]);
            }
        }

        // ---- causal mask (diagonal tile only) ----
        if (kt == qt) {
            int rbase = q0 + wm * 16 + (lane >> 2);
            int cbase = k0 + (lane & 3) * 2;
#pragma unroll
            for (int j = 0; j < 8; j++) {
                int c0 = cbase + j * 8, c1 = c0 + 1;
                if (c0 > rbase)     s[j][0] = -1e30f;
                if (c1 > rbase)     s[j][1] = -1e30f;
                if (c0 > rbase + 8) s[j][2] = -1e30f;
                if (c1 > rbase + 8) s[j][3] = -1e30f;
            }
        }

        // ---- online softmax ----
        float mt0 = -1e30f, mt1 = -1e30f;
#pragma unroll
        for (int j = 0; j < 8; j++) {
            mt0 = fmaxf(mt0, fmaxf(s[j][0], s[j][1]));
            mt1 = fmaxf(mt1, fmaxf(s[j][2], s[j][3]));
        }
        mt0 = fmaxf(mt0, __shfl_xor_sync(0xffffffffu, mt0, 1));
        mt0 = fmaxf(mt0, __shfl_xor_sync(0xffffffffu, mt0, 2));
        mt1 = fmaxf(mt1, __shfl_xor_sync(0xffffffffu, mt1, 1));
        mt1 = fmaxf(mt1, __shfl_xor_sync(0xffffffffu, mt1, 2));
        float mn0 = fmaxf(m0, mt0), mn1 = fmaxf(m1, mt1);
        float cr0 = __expf(m0 - mn0), cr1 = __expf(m1 - mn1);
        m0 = mn0; m1 = mn1;

        float ps0 = 0.0f, ps1 = 0.0f;
#pragma unroll
        for (int j = 0; j < 8; j++) {
            s[j][0] = __expf(s[j][0] - mn0);
            s[j][1] = __expf(s[j][1] - mn0);
            s[j][2] = __expf(s[j][2] - mn1);
            s[j][3] = __expf(s[j][3] - mn1);
            ps0 += s[j][0] + s[j][1];
            ps1 += s[j][2] + s[j][3];
        }
        ps0 += __shfl_xor_sync(0xffffffffu, ps0, 1);
        ps0 += __shfl_xor_sync(0xffffffffu, ps0, 2);
        ps1 += __shfl_xor_sync(0xffffffffu, ps1, 1);
        ps1 += __shfl_xor_sync(0xffffffffu, ps1, 2);
        l0 = l0 * cr0 + ps0;
        l1 = l1 * cr1 + ps1;
#pragma unroll
        for (int j = 0; j < 16; j++) {
            o[j][0] *= cr0; o[j][1] *= cr0;
            o[j][2] *= cr1; o[j][3] *= cr1;
        }

        // ---- P -> bf16 hi/lo A-fragments ----
        uint32_t phi[4][4], plo[4][4];
#pragma unroll
        for (int ks = 0; ks < 4; ks++) {
            bsplit2(s[2 * ks][0],     s[2 * ks][1],     phi[ks][0], plo[ks][0]);
            bsplit2(s[2 * ks][2],     s[2 * ks][3],     phi[ks][1], plo[ks][1]);
            bsplit2(s[2 * ks + 1][0], s[2 * ks + 1][1], phi[ks][2], plo[ks][2]);
            bsplit2(s[2 * ks + 1][2], s[2 * ks + 1][3], phi[ks][3], plo[ks][3]);
        }

        // ---- O += P @ V (3-term split), B = Vt tiles ----
#pragma unroll
        for (int v2 = 0; v2 < 8; v2++) {
            int rv = v2 * 16 + qb0 * 8 + rr;
            uint32_t vbase = stg + 32768 + rv * 128;
            int swv = rv & 7;
#pragma unroll
            for (int ks = 0; ks < 4; ks++) {
                uint32_t u = 2 * ks + qb1;
                uint32_t voff = (u ^ swv) << 4;
                uint32_t bh[4], bl[4];
                ldmx4(bh, vbase + voff);
                ldmx4(bl, vbase + 16384 + voff);
                float* o0 = o[v2 * 2];
                float* o1 = o[v2 * 2 + 1];
                mma16816(o0, phi[ks], bh[0], bh[1]);
                mma16816(o0, phi[ks], bl[0], bl[1]);
                mma16816(o0, plo[ks], bh[0], bh[1]);
                mma16816(o1, phi[ks], bh[2], bh[3]);
                mma16816(o1, phi[ks], bl[2], bl[3]);
                mma16816(o1, plo[ks], bh[2], bh[3]);
            }
        }

        if (kt + 2 <= qt) {
            __syncthreads();
            attn_load_tile(sb + 32768 + (kt & 1) * 65536, tid, b, h, (kt + 2) * 64,
                           Kh, Kl, Vth, Vtl);
        }
    }

    // ---- epilogue ----
    float inv0 = 1.0f / l0, inv1 = 1.0f / l1;
    int row0 = b * S_LEN + q0 + wm * 16 + (lane >> 2);
    int colb = h * HD + (lane & 3) * 2;
#pragma unroll
    for (int j = 0; j < 16; j++) {
        *(float2*)(Y + (size_t)row0 * HIDDEN + colb + j * 8)
            = make_float2(o[j][0] * inv0, o[j][1] * inv0);
        *(float2*)(Y + (size_t)(row0 + 8) * HIDDEN + colb + j * 8)
            = make_float2(o[j][2] * inv1, o[j][3] * inv1);
    }
}

// ---------------- host ----------------
static void launch_mma(const __nv_bfloat16* Ah, const __nv_bfloat16* Al,
                       const __nv_bfloat16* Bh, const __nv_bfloat16* Bl,
                       float* C, int M, int N, int K)
{
    dim3 grid(N / 128, M / 128);
    hmma_gemm_kernel<<<grid, 256, G_SMEM>>>(Ah, Al, Bh, Bl, C, M, N, K);
}

extern "C" void kernel_launch(void* const* d_in, const int* in_sizes, int n_in,
                              void* d_out, int out_size)
{
    const float* x        = (const float*)d_in[0];
    const float* W_kv_d   = (const float*)d_in[1];
    const float* W_q_d    = (const float*)d_in[2];
    const float* W_k_u    = (const float*)d_in[3];
    const float* W_q_u    = (const float*)d_in[4];
    const float* W_v_u    = (const float*)d_in[5];
    const float* W_rope_k = (const float*)d_in[6];
    const float* W_rope_q = (const float*)d_in[7];
    const float* W_o      = (const float*)d_in[8];
    float* out = (float*)d_out;

    float *kv_lat, *q_lat, *k_half, *q_half, *k_rope, *q_rope, *V, *Y, *cosT, *sinT;
    __nv_bfloat16 *xbh, *xbl, *kvbh, *kvbl, *qbh, *qbl, *wbh, *wbl;
    __nv_bfloat16 *Qh, *Ql, *Kh, *Kl, *Vth, *Vtl;
    cudaGetSymbolAddress((void**)&kv_lat, g_kv_lat);
    cudaGetSymbolAddress((void**)&q_lat,  g_q_lat);
    cudaGetSymbolAddress((void**)&k_half, g_k_half);
    cudaGetSymbolAddress((void**)&q_half, g_q_half);
    cudaGetSymbolAddress((void**)&k_rope, g_k_rope);
    cudaGetSymbolAddress((void**)&q_rope, g_q_rope);
    cudaGetSymbolAddress((void**)&V,      g_v);
    cudaGetSymbolAddress((void**)&Y,      g_y);
    cudaGetSymbolAddress((void**)&cosT,   g_cos);
    cudaGetSymbolAddress((void**)&sinT,   g_sin);
    cudaGetSymbolAddress((void**)&xbh,    g_xb_hi);
    cudaGetSymbolAddress((void**)&xbl,    g_xb_lo);
    cudaGetSymbolAddress((void**)&kvbh,   g_kvb_hi);
    cudaGetSymbolAddress((void**)&kvbl,   g_kvb_lo);
    cudaGetSymbolAddress((void**)&qbh,    g_qb_hi);
    cudaGetSymbolAddress((void**)&qbl,    g_qb_lo);
    cudaGetSymbolAddress((void**)&wbh,    g_wb_hi);
    cudaGetSymbolAddress((void**)&wbl,    g_wb_lo);
    cudaGetSymbolAddress((void**)&Qh,     g_Qh);
    cudaGetSymbolAddress((void**)&Ql,     g_Ql);
    cudaGetSymbolAddress((void**)&Kh,     g_Kh);
    cudaGetSymbolAddress((void**)&Kl,     g_Kl);
    cudaGetSymbolAddress((void**)&Vth,    g_Vth);
    cudaGetSymbolAddress((void**)&Vtl,    g_Vtl);

    cudaFuncSetAttribute(hmma_gemm_kernel, cudaFuncAttributeMaxDynamicSharedMemorySize, G_SMEM);
    cudaFuncSetAttribute(fattn_kernel, cudaFuncAttributeMaxDynamicSharedMemorySize, A_SMEM);

    rope_table_kernel<<<(S_LEN * 32 + 255) / 256, 256>>>(cosT, sinT);

    // weight conversions (fp32 [K,N] -> bf16 hi/lo [N,K])
    dim3 wb(32, 8);
    wconv_kernel<<<dim3( 512/32, 2048/32), wb>>>(W_kv_d,   wbh + OFF_KV_D,   wbl + OFF_KV_D,   2048,  512);
    wconv_kernel<<<dim3( 512/32, 2048/32), wb>>>(W_q_d,    wbh + OFF_Q_D,    wbl + OFF_Q_D,    2048,  512);
    wconv_kernel<<<dim3(1024/32, 2048/32), wb>>>(W_rope_k, wbh + OFF_ROPE_K, wbl + OFF_ROPE_K, 2048, 1024);
    wconv_kernel<<<dim3(1024/32,  512/32), wb>>>(W_k_u,    wbh + OFF_K_U,    wbl + OFF_K_U,     512, 1024);
    wconv_kernel<<<dim3(1024/32,  512/32), wb>>>(W_q_u,    wbh + OFF_Q_U,    wbl + OFF_Q_U,     512, 1024);
    wconv_kernel<<<dim3(1024/32,  512/32), wb>>>(W_rope_q, wbh + OFF_ROPE_Q, wbl + OFF_ROPE_Q,  512, 1024);
    wconv_kernel<<<dim3(2048/32,  512/32), wb>>>(W_v_u,    wbh + OFF_V_U,    wbl + OFF_V_U,     512, 2048);
    wconv_kernel<<<dim3(2048/32, 2048/32), wb>>>(W_o,      wbh + OFF_O,      wbl + OFF_O,      2048, 2048);

    // x -> bf16 split
    aconv_kernel<<<(M_TOT * HIDDEN / 4 + 255) / 256, 256>>>(x, xbh, xbl, M_TOT * HIDDEN / 4);

    // level 1 GEMMs (K=2048)
    launch_mma(xbh, xbl, wbh + OFF_KV_D,   wbl + OFF_KV_D,   kv_lat, M_TOT,  512, 2048);
    launch_mma(xbh, xbl, wbh + OFF_Q_D,    wbl + OFF_Q_D,    q_lat,  M_TOT,  512, 2048);
    launch_mma(xbh, xbl, wbh + OFF_ROPE_K, wbl + OFF_ROPE_K, k_rope, M_TOT, 1024, 2048);

    // latents -> bf16 split
    aconv_kernel<<<(M_TOT * LATENT / 4 + 255) / 256, 256>>>(kv_lat, kvbh, kvbl, M_TOT * LATENT / 4);
    aconv_kernel<<<(M_TOT * LATENT / 4 + 255) / 256, 256>>>(q_lat,  qbh,  qbl,  M_TOT * LATENT / 4);

    // level 2 GEMMs (K=512)
    launch_mma(kvbh, kvbl, wbh + OFF_K_U,    wbl + OFF_K_U,    k_half, M_TOT, 1024, 512);
    launch_mma(qbh,  qbl,  wbh + OFF_Q_U,    wbl + OFF_Q_U,    q_half, M_TOT, 1024, 512);
    launch_mma(qbh,  qbl,  wbh + OFF_ROPE_Q, wbl + OFF_ROPE_Q, q_rope, M_TOT, 1024, 512);
    launch_mma(kvbh, kvbl, wbh + OFF_V_U,    wbl + OFF_V_U,    V,      M_TOT, 2048, 512);

    // V -> Vt bf16 hi/lo; q/k assemble -> bf16 hi/lo (Q prescaled)
    vtconv_kernel<<<dim3(S_LEN / 32, HD / 32, B_SZ * NH), wb>>>(V, Vth, Vtl);
    assemble_qk_kernel<<<(M_TOT * 1024 + 255) / 256, 256>>>(
        q_half, q_rope, k_half, k_rope, cosT, sinT, Qh, Ql, Kh, Kl);

    // HMMA flash attention
    dim3 agrid(S_LEN / 64, NH, B_SZ);
    fattn_kernel<<<agrid, 128, A_SMEM>>>(Qh, Ql, Kh, Kl, Vth, Vtl, Y);

    // Y -> bf16 split, output projection
    aconv_kernel<<<(M_TOT * HIDDEN / 4 + 255) / 256, 256>>>(Y, xbh, xbl, M_TOT * HIDDEN / 4);
    launch_mma(xbh, xbl, wbh + OFF_O, wbl + OFF_O, out, M_TOT, 2048, 2048);
}